// round 1
// baseline (speedup 1.0000x reference)
#include <cuda_runtime.h>
#include <math.h>

#define BQ   8
#define TT   1024
#define DM   1024
#define NH   16
#define DKK  64
#define FFI  4096
#define BT   (BQ*TT)   // 8192 rows
#define BHN  (BQ*NH)   // 128 (b,h) pairs

// ---------------- scratch (static device globals; no runtime alloc) -------------
__device__ float g_Wqr[DM*DM];            // repacked [D][H*dk]
__device__ float g_Wkr[DM*DM];
__device__ float g_Wvr[DM*DM];
__device__ float g_W1r[DM*FFI];           // [D][FF]
__device__ float g_W2r[FFI*DM];           // [FF][D]
__device__ float g_Q[BT*DM];              // row-major [bt][h*64+k]
__device__ float g_K[BT*DM];
__device__ float g_V[BT*DM];
__device__ float g_S[(size_t)BHN*TT*TT];  // 512 MB scores scratch
__device__ float g_m[BHN*TT];             // per-(bh,s) column max
__device__ float g_zinv[BHN*TT];          // per-(bh,s) 1/sum(exp)
__device__ float g_part[BT*DM];           // concat heads
__device__ float g_out1[BT*DM];           // out1 (normed in-place)
__device__ float g_ffh[(size_t)BT*FFI];   // FF hidden
__device__ float g_out2[BT*DM];           // pre-norm out2

// ---------------- repacks -------------------------------------------------------
__global__ void __launch_bounds__(256) repack_qkv(const float* __restrict__ Wq,
                                                  const float* __restrict__ Wk,
                                                  const float* __restrict__ Wv) {
    int i = blockIdx.x * 256 + threadIdx.x;       // over DM*DM, i = d*1024 + (h*64+k)
    int d = i >> 10, c = i & 1023;
    int h = c >> 6, k = c & 63;
    int src = (h * DM + d) * DKK + k;             // Wq[h][d][k]
    g_Wqr[i] = Wq[src];
    g_Wkr[i] = Wk[src];
    g_Wvr[i] = Wv[src];
}

__global__ void __launch_bounds__(256) repack_w1(const float* __restrict__ W1) {
    int i = blockIdx.x * 256 + threadIdx.x;       // i = d*FFI + f
    int d = i >> 12, f = i & 4095;
    g_W1r[i] = W1[f * DM + d];                    // W1[f][d]
}

__global__ void __launch_bounds__(256) repack_w2(const float* __restrict__ W2) {
    int i = blockIdx.x * 256 + threadIdx.x;       // i = f*DM + d
    int f = i >> 10, d = i & 1023;
    g_W2r[i] = W2[d * FFI + f];                   // W2[d][f]
}

// ---------------- generic tiled SGEMM: C[M,N] = A[M,K]*B[K,N] (+epilogue) --------
// EPI: 0 none, 1 +res, 2 relu(+bias), 3 +bias+res
template <int EPI>
__global__ void __launch_bounds__(256) sgemm128(
    const float* __restrict__ A, int lda,
    const float* __restrict__ B, int ldb,
    float* __restrict__ C, int ldc,
    int K,
    const float* __restrict__ bias,
    const float* __restrict__ res, int ldres)
{
    __shared__ float As[8][128];  // [kk][row]
    __shared__ float Bs[8][128];  // [kk][col]
    const int tid = threadIdx.x;
    const int tx = tid & 15, ty = tid >> 4;
    const int rowBase = blockIdx.y * 128;
    const int colBase = blockIdx.x * 128;

    float acc[8][8] = {};

    const int arow = tid >> 1;            // 0..127
    const int akk  = (tid & 1) * 4;       // 0 or 4
    const int bkk  = tid >> 5;            // 0..7
    const int bcol = (tid & 31) * 4;

    const float* Aptr = A + (size_t)(rowBase + arow) * lda + akk;
    const float* Bptr = B + (size_t)bkk * ldb + colBase + bcol;

    for (int k0 = 0; k0 < K; k0 += 8) {
        float4 av = *(const float4*)(Aptr + k0);
        float4 bv = *(const float4*)(Bptr + (size_t)k0 * ldb);
        __syncthreads();
        As[akk + 0][arow] = av.x;
        As[akk + 1][arow] = av.y;
        As[akk + 2][arow] = av.z;
        As[akk + 3][arow] = av.w;
        *(float4*)&Bs[bkk][bcol] = bv;
        __syncthreads();
#pragma unroll
        for (int kk = 0; kk < 8; kk++) {
            float a[8], b[8];
            *(float4*)(a)     = *(const float4*)&As[kk][ty * 8];
            *(float4*)(a + 4) = *(const float4*)&As[kk][ty * 8 + 4];
            *(float4*)(b)     = *(const float4*)&Bs[kk][tx * 8];
            *(float4*)(b + 4) = *(const float4*)&Bs[kk][tx * 8 + 4];
#pragma unroll
            for (int i = 0; i < 8; i++)
#pragma unroll
                for (int j = 0; j < 8; j++)
                    acc[i][j] = fmaf(a[i], b[j], acc[i][j]);
        }
    }

#pragma unroll
    for (int i = 0; i < 8; i++) {
        int row = rowBase + ty * 8 + i;
#pragma unroll
        for (int j = 0; j < 8; j++) {
            int col = colBase + tx * 8 + j;
            float v = acc[i][j];
            if (EPI == 1) v += res[(size_t)row * ldres + col];
            if (EPI == 2) v = fmaxf(v + bias[col], 0.f);
            if (EPI == 3) v += bias[col] + res[(size_t)row * ldres + col];
            C[(size_t)row * ldc + col] = v;
        }
    }
}

// ---------------- scores: S[bh][q][s] = (Q_bh . K_bh^T) / 8 ---------------------
__global__ void __launch_bounds__(256) scores_kernel() {
    int bh = blockIdx.z;
    int b = bh >> 4, h = bh & 15;
    int q0 = blockIdx.y * 64, s0 = blockIdx.x * 64;
    __shared__ float Qs[64][68];  // [k][q]
    __shared__ float Ks[64][68];  // [k][s]
    const float* Qb = g_Q + (size_t)(b * TT) * DM + h * DKK;
    const float* Kb = g_K + (size_t)(b * TT) * DM + h * DKK;
    int tid = threadIdx.x;
#pragma unroll
    for (int j = 0; j < 4; j++) {
        int idx = tid + j * 256;
        int r = idx >> 4;
        int f4 = (idx & 15) * 4;
        float4 qv = *(const float4*)(Qb + (size_t)(q0 + r) * DM + f4);
        Qs[f4 + 0][r] = qv.x; Qs[f4 + 1][r] = qv.y;
        Qs[f4 + 2][r] = qv.z; Qs[f4 + 3][r] = qv.w;
        float4 kv = *(const float4*)(Kb + (size_t)(s0 + r) * DM + f4);
        Ks[f4 + 0][r] = kv.x; Ks[f4 + 1][r] = kv.y;
        Ks[f4 + 2][r] = kv.z; Ks[f4 + 3][r] = kv.w;
    }
    __syncthreads();
    int tx = tid & 15, ty = tid >> 4;
    float acc[4][4] = {};
#pragma unroll
    for (int k = 0; k < 64; k++) {
        float a[4], bb[4];
        *(float4*)a  = *(const float4*)&Qs[k][ty * 4];
        *(float4*)bb = *(const float4*)&Ks[k][tx * 4];
#pragma unroll
        for (int i = 0; i < 4; i++)
#pragma unroll
            for (int j = 0; j < 4; j++)
                acc[i][j] = fmaf(a[i], bb[j], acc[i][j]);
    }
    float* Sout = g_S + (size_t)bh * TT * TT;
#pragma unroll
    for (int i = 0; i < 4; i++)
#pragma unroll
        for (int j = 0; j < 4; j++)
            Sout[(size_t)(q0 + ty * 4 + i) * TT + s0 + tx * 4 + j] = acc[i][j] * 0.125f;
}

// ---------------- column softmax stats (over q axis!) ---------------------------
__global__ void __launch_bounds__(256) softmax_stats() {
    int bh = blockIdx.y;
    int s = blockIdx.x * 256 + threadIdx.x;
    const float* Sb = g_S + (size_t)bh * TT * TT + s;
    float m = -3.4e38f;
#pragma unroll 8
    for (int q = 0; q < TT; q++) m = fmaxf(m, Sb[(size_t)q * TT]);
    float z = 0.f;
#pragma unroll 8
    for (int q = 0; q < TT; q++) z += __expf(Sb[(size_t)q * TT] - m);
    g_m[bh * TT + s] = m;
    g_zinv[bh * TT + s] = 1.f / z;
}

// ---------------- part[q,v] = sum_s softmaxQ(S)[q,s] * V[s,v] -------------------
__global__ void __launch_bounds__(256) av_kernel() {
    int bh = blockIdx.y;
    int b = bh >> 4, h = bh & 15;
    int q0 = blockIdx.x * 64;
    __shared__ float As[32][68];  // [s][q] (exp-normalized)
    __shared__ float Vs[32][64];  // [s][v]
    const float* Sb = g_S + (size_t)bh * TT * TT;
    const float* Vb = g_V + (size_t)(b * TT) * DM + h * DKK;
    const float* mb = g_m + bh * TT;
    const float* zb = g_zinv + bh * TT;
    int tid = threadIdx.x, tx = tid & 15, ty = tid >> 4;
    float acc[4][4] = {};
    for (int s0 = 0; s0 < TT; s0 += 32) {
        __syncthreads();
#pragma unroll
        for (int j = 0; j < 2; j++) {
            int idx = tid + j * 256;
            int q = idx >> 3, f4 = (idx & 7) * 4;
            float4 sv = *(const float4*)(Sb + (size_t)(q0 + q) * TT + s0 + f4);
            As[f4 + 0][q] = __expf(sv.x - mb[s0 + f4 + 0]) * zb[s0 + f4 + 0];
            As[f4 + 1][q] = __expf(sv.y - mb[s0 + f4 + 1]) * zb[s0 + f4 + 1];
            As[f4 + 2][q] = __expf(sv.z - mb[s0 + f4 + 2]) * zb[s0 + f4 + 2];
            As[f4 + 3][q] = __expf(sv.w - mb[s0 + f4 + 3]) * zb[s0 + f4 + 3];
            int sv2 = idx >> 4, vf = (idx & 15) * 4;
            *(float4*)&Vs[sv2][vf] = *(const float4*)(Vb + (size_t)(s0 + sv2) * DM + vf);
        }
        __syncthreads();
#pragma unroll
        for (int ss = 0; ss < 32; ss++) {
            float a[4], vv[4];
            *(float4*)a  = *(const float4*)&As[ss][ty * 4];
            *(float4*)vv = *(const float4*)&Vs[ss][tx * 4];
#pragma unroll
            for (int i = 0; i < 4; i++)
#pragma unroll
                for (int j = 0; j < 4; j++)
                    acc[i][j] = fmaf(a[i], vv[j], acc[i][j]);
        }
    }
#pragma unroll
    for (int i = 0; i < 4; i++)
#pragma unroll
        for (int j = 0; j < 4; j++)
            g_part[(size_t)(b * TT + q0 + ty * 4 + i) * DM + h * DKK + tx * 4 + j] = acc[i][j];
}

// ---------------- pseudo-norm: y - mean - std(ddof=1), per row of 1024 ----------
__global__ void __launch_bounds__(256) pnorm_kernel(const float* __restrict__ in,
                                                    float* __restrict__ out) {
    int row = blockIdx.x;
    const float* p = in + (size_t)row * DM;
    float s = 0.f, s2 = 0.f;
    for (int i = threadIdx.x; i < DM; i += 256) {
        float v = p[i];
        s += v;
        s2 = fmaf(v, v, s2);
    }
    __shared__ float sh[2][8];
#pragma unroll
    for (int o = 16; o > 0; o >>= 1) {
        s  += __shfl_down_sync(0xffffffffu, s, o);
        s2 += __shfl_down_sync(0xffffffffu, s2, o);
    }
    int wid = threadIdx.x >> 5, lane = threadIdx.x & 31;
    if (lane == 0) { sh[0][wid] = s; sh[1][wid] = s2; }
    __syncthreads();
    __shared__ float bsub;
    if (threadIdx.x == 0) {
        float ts = 0.f, ts2 = 0.f;
#pragma unroll
        for (int i = 0; i < 8; i++) { ts += sh[0][i]; ts2 += sh[1][i]; }
        float mean = ts * (1.f / 1024.f);
        float var = (ts2 - 1024.f * mean * mean) * (1.f / 1023.f);
        bsub = mean + sqrtf(fmaxf(var, 0.f));
    }
    __syncthreads();
    float sub = bsub;
    for (int i = threadIdx.x; i < DM; i += 256)
        out[(size_t)row * DM + i] = p[i] - sub;
}

// ---------------- launch --------------------------------------------------------
extern "C" void kernel_launch(void* const* d_in, const int* in_sizes, int n_in,
                              void* d_out, int out_size) {
    const float* x  = (const float*)d_in[0];
    const float* Wq = (const float*)d_in[1];
    const float* Wk = (const float*)d_in[2];
    const float* Wv = (const float*)d_in[3];
    const float* Wo = (const float*)d_in[4];
    const float* W1 = (const float*)d_in[5];
    const float* b1 = (const float*)d_in[6];
    const float* W2 = (const float*)d_in[7];
    const float* b2 = (const float*)d_in[8];
    float* out = (float*)d_out;

    float *pWqr, *pWkr, *pWvr, *pW1r, *pW2r, *pQ, *pK, *pV, *pPart, *pOut1, *pFfh, *pOut2;
    cudaGetSymbolAddress((void**)&pWqr,  g_Wqr);
    cudaGetSymbolAddress((void**)&pWkr,  g_Wkr);
    cudaGetSymbolAddress((void**)&pWvr,  g_Wvr);
    cudaGetSymbolAddress((void**)&pW1r,  g_W1r);
    cudaGetSymbolAddress((void**)&pW2r,  g_W2r);
    cudaGetSymbolAddress((void**)&pQ,    g_Q);
    cudaGetSymbolAddress((void**)&pK,    g_K);
    cudaGetSymbolAddress((void**)&pV,    g_V);
    cudaGetSymbolAddress((void**)&pPart, g_part);
    cudaGetSymbolAddress((void**)&pOut1, g_out1);
    cudaGetSymbolAddress((void**)&pFfh,  g_ffh);
    cudaGetSymbolAddress((void**)&pOut2, g_out2);

    // weight repacks
    repack_qkv<<<DM * DM / 256, 256>>>(Wq, Wk, Wv);
    repack_w1<<<DM * FFI / 256, 256>>>(W1);
    repack_w2<<<FFI * DM / 256, 256>>>(W2);

    // QKV projections: [8192,1024] x [1024,1024]
    dim3 gq(DM / 128, BT / 128);
    sgemm128<0><<<gq, 256>>>(x, DM, pWqr, DM, pQ, DM, DM, nullptr, nullptr, 0);
    sgemm128<0><<<gq, 256>>>(x, DM, pWkr, DM, pK, DM, DM, nullptr, nullptr, 0);
    sgemm128<0><<<gq, 256>>>(x, DM, pWvr, DM, pV, DM, DM, nullptr, nullptr, 0);

    // attention
    scores_kernel<<<dim3(16, 16, BHN), 256>>>();
    softmax_stats<<<dim3(TT / 256, BHN), 256>>>();
    av_kernel<<<dim3(TT / 64, BHN), 256>>>();

    // Wo projection + residual, then pseudo-norm in place
    sgemm128<1><<<gq, 256>>>(pPart, DM, Wo, DM, pOut1, DM, DM, nullptr, x, DM);
    pnorm_kernel<<<BT, 256>>>(pOut1, pOut1);

    // FF
    dim3 gff(FFI / 128, BT / 128);
    sgemm128<2><<<gff, 256>>>(pOut1, DM, pW1r, FFI, pFfh, FFI, DM, b1, nullptr, 0);
    sgemm128<3><<<gq, 256>>>(pFfh, FFI, pW2r, DM, pOut2, DM, FFI, b2, pOut1, DM);

    // final pseudo-norm -> output
    pnorm_kernel<<<BT, 256>>>(pOut2, out);
}

// round 3
// speedup vs baseline: 2.2627x; 2.2627x over previous
#include <cuda_runtime.h>
#include <cstdint>
#include <math.h>

#define BQ   8
#define TT   1024
#define DM   1024
#define NH   16
#define DKK  64
#define FFI  4096
#define BT   (BQ*TT)   // 8192 rows
#define BHN  (BQ*NH)   // 128 (b,h) pairs

// ---------------- scratch (static device globals; no runtime alloc) -------------
__device__ float g_xr[BT*DM];             // tf32-rounded x
__device__ float g_Wqr[DM*DM];            // [n=h*64+kk][k=d], tf32-rounded
__device__ float g_Wkr[DM*DM];
__device__ float g_Wvr[DM*DM];
__device__ float g_Wor[DM*DM];            // [n][k] = Wo^T, rounded
__device__ float g_W1r[FFI*DM];           // rounded copy of W1 [f][d]
__device__ float g_W2r[DM*FFI];           // rounded copy of W2 [d][f]
__device__ float g_Q[BT*DM];
__device__ float g_K[BT*DM];
__device__ float g_V[BT*DM];
__device__ float g_S[(size_t)BHN*TT*TT];  // 512 MB scores scratch
__device__ float g_m[BHN*TT];
__device__ float g_zinv[BHN*TT];
__device__ float g_part[BT*DM];           // rounded in av epilogue
__device__ float g_out1[BT*DM];
__device__ float g_ffh[(size_t)BT*FFI];
__device__ float g_out2[BT*DM];

// ================= helpers =======================================================
__device__ __forceinline__ uint32_t smem_to_u32(const void* p) {
    uint32_t a;
    asm("{ .reg .u64 t; cvta.to.shared.u64 t, %1; cvt.u32.u64 %0, t; }" : "=r"(a) : "l"(p));
    return a;
}
__device__ __forceinline__ uint32_t f2tf(float f) {
    uint32_t u;
    asm("cvt.rna.tf32.f32 %0, %1;" : "=r"(u) : "f"(f));
    return u;
}
__device__ __forceinline__ float rtf(float f) { return __uint_as_float(f2tf(f)); }

__device__ __forceinline__ void cpasync16(uint32_t dst, const void* src) {
    asm volatile("cp.async.cg.shared.global [%0], [%1], 16;" :: "r"(dst), "l"(src));
}
#define CP_COMMIT() asm volatile("cp.async.commit_group;" ::: "memory")
#define CP_WAIT(n)  asm volatile("cp.async.wait_group %0;" :: "n"(n) : "memory")

__device__ __forceinline__ void mma_tf32(float* c, uint32_t a0, uint32_t a1,
                                         uint32_t a2, uint32_t a3,
                                         uint32_t b0, uint32_t b1) {
    asm volatile(
        "mma.sync.aligned.m16n8k8.row.col.f32.tf32.tf32.f32 "
        "{%0,%1,%2,%3}, {%4,%5,%6,%7}, {%8,%9}, {%0,%1,%2,%3};"
        : "+f"(c[0]), "+f"(c[1]), "+f"(c[2]), "+f"(c[3])
        : "r"(a0), "r"(a1), "r"(a2), "r"(a3), "r"(b0), "r"(b1));
}

// ================= mma.sync tf32 GEMM: C[M,N] = A[M,K] * B[N,K]^T (+epi) ========
// Block 128x128, 8 warps (2x4), warp tile 64x32, K-step 32, cp.async double buf.
// SMEM rows padded to 36 words. EPI: 0 none, 1 +res, 2 relu(+bias)+round, 3 +bias+res
#define GM_SMEM_BYTES 73728   // 2 * (18432 A + 18432 B)

template <int EPI>
__global__ void __launch_bounds__(256, 2) gemm_mma(
    const float* __restrict__ A, int lda,
    const float* __restrict__ B, int ldb,
    float* __restrict__ C, int ldc,
    int K,
    const float* __restrict__ bias,
    const float* __restrict__ res, int ldres)
{
    extern __shared__ uint32_t smem[];   // word-indexed
    const int tid = threadIdx.x;
    const int wid = tid >> 5, lane = tid & 31;
    const int wm = wid >> 2, wn = wid & 3;
    const int grp = lane >> 2, kq = lane & 3;
    const int m0 = blockIdx.y * 128, n0 = blockIdx.x * 128;

    const float* Ab = A + (size_t)m0 * lda;
    const float* Bb = B + (size_t)n0 * ldb;
    const uint32_t sbase = smem_to_u32(smem);

    float acc[4][4][4] = {};
    const int NC = K / 32;

    const int lr = tid >> 3;           // 0..31 row group per j
    const int lc = (tid & 7) * 4;      // float col

    // issue cp.async for chunk c into buffer buf
    auto issue = [&](int c, int buf) {
        const int k0 = c * 32;
        const uint32_t sA = sbase + buf * 36864u;
        const uint32_t sB = sA + 18432u;
#pragma unroll
        for (int j = 0; j < 4; j++) {
            int rr = lr + j * 32;
            cpasync16(sA + rr * 144u + (lc * 4u), Ab + (size_t)rr * lda + k0 + lc);
            cpasync16(sB + rr * 144u + (lc * 4u), Bb + (size_t)rr * ldb + k0 + lc);
        }
    };

    issue(0, 0);
    CP_COMMIT();

    for (int c = 0; c < NC; c++) {
        const int buf = c & 1;
        if (c + 1 < NC) {
            issue(c + 1, buf ^ 1);
            CP_COMMIT();
            CP_WAIT(1);
        } else {
            CP_WAIT(0);
        }
        __syncthreads();

        const uint32_t* As = smem + buf * 9216;
        const uint32_t* Bs = As + 4608;
#pragma unroll
        for (int ks = 0; ks < 4; ks++) {
            const int k0 = ks * 8;
            uint32_t bf[4][2];
#pragma unroll
            for (int ni = 0; ni < 4; ni++) {
                int nrow = wn * 32 + ni * 8 + grp;
                bf[ni][0] = Bs[nrow * 36 + k0 + kq];
                bf[ni][1] = Bs[nrow * 36 + k0 + kq + 4];
            }
#pragma unroll
            for (int mi = 0; mi < 4; mi++) {
                int mrow = wm * 64 + mi * 16 + grp;
                uint32_t a0 = As[mrow * 36 + k0 + kq];
                uint32_t a1 = As[(mrow + 8) * 36 + k0 + kq];
                uint32_t a2 = As[mrow * 36 + k0 + kq + 4];
                uint32_t a3 = As[(mrow + 8) * 36 + k0 + kq + 4];
#pragma unroll
                for (int ni = 0; ni < 4; ni++)
                    mma_tf32(acc[mi][ni], a0, a1, a2, a3, bf[ni][0], bf[ni][1]);
            }
        }
        __syncthreads();
    }

    // epilogue: direct float2 stores
#pragma unroll
    for (int mi = 0; mi < 4; mi++) {
        int row = m0 + wm * 64 + mi * 16 + grp;
#pragma unroll
        for (int ni = 0; ni < 4; ni++) {
            int col = n0 + wn * 32 + ni * 8 + kq * 2;
            float v00 = acc[mi][ni][0], v01 = acc[mi][ni][1];
            float v10 = acc[mi][ni][2], v11 = acc[mi][ni][3];
            if (EPI == 1 || EPI == 3) {
                float2 r0 = *(const float2*)(res + (size_t)row * ldres + col);
                float2 r1 = *(const float2*)(res + (size_t)(row + 8) * ldres + col);
                v00 += r0.x; v01 += r0.y; v10 += r1.x; v11 += r1.y;
            }
            if (EPI == 2) {
                float b0 = bias[col], b1 = bias[col + 1];
                v00 = rtf(fmaxf(v00 + b0, 0.f));
                v01 = rtf(fmaxf(v01 + b1, 0.f));
                v10 = rtf(fmaxf(v10 + b0, 0.f));
                v11 = rtf(fmaxf(v11 + b1, 0.f));
            }
            if (EPI == 3) {
                float b0 = bias[col], b1 = bias[col + 1];
                v00 += b0; v01 += b1; v10 += b0; v11 += b1;
            }
            float2 o0 = {v00, v01}, o1 = {v10, v11};
            *(float2*)(C + (size_t)row * ldc + col) = o0;
            *(float2*)(C + (size_t)(row + 8) * ldc + col) = o1;
        }
    }
}

// ---------------- producers / repacks (all tf32-round their outputs) ------------
__global__ void __launch_bounds__(256) round_x(const float* __restrict__ x) {
    int i = blockIdx.x * 256 + threadIdx.x;
    g_xr[i] = rtf(x[i]);
}
__global__ void __launch_bounds__(256) repack_qkv(const float* __restrict__ Wq,
                                                  const float* __restrict__ Wk,
                                                  const float* __restrict__ Wv) {
    int i = blockIdx.x * 256 + threadIdx.x;   // i = n*1024 + d
    int n = i >> 10, d = i & 1023;
    int h = n >> 6, kk = n & 63;
    int src = (h * DM + d) * DKK + kk;
    g_Wqr[i] = rtf(Wq[src]);
    g_Wkr[i] = rtf(Wk[src]);
    g_Wvr[i] = rtf(Wv[src]);
}
__global__ void __launch_bounds__(256) repack_wo(const float* __restrict__ Wo) {
    int i = blockIdx.x * 256 + threadIdx.x;   // i = n*1024 + k
    int n = i >> 10, k = i & 1023;
    g_Wor[i] = rtf(Wo[k * DM + n]);
}
__global__ void __launch_bounds__(256) repack_w12(const float* __restrict__ W1,
                                                  const float* __restrict__ W2) {
    int i = blockIdx.x * 256 + threadIdx.x;   // over FFI*DM
    g_W1r[i] = rtf(W1[i]);
    g_W2r[i] = rtf(W2[i]);
}

// ---------------- scores: S[bh][q][s] = (Q_bh . K_bh^T) / 8 ---------------------
__global__ void __launch_bounds__(256) scores_kernel() {
    int bh = blockIdx.z;
    int b = bh >> 4, h = bh & 15;
    int q0 = blockIdx.y * 64, s0 = blockIdx.x * 64;
    __shared__ float Qs[64][68];
    __shared__ float Ks[64][68];
    const float* Qb = g_Q + (size_t)(b * TT) * DM + h * DKK;
    const float* Kb = g_K + (size_t)(b * TT) * DM + h * DKK;
    int tid = threadIdx.x;
#pragma unroll
    for (int j = 0; j < 4; j++) {
        int idx = tid + j * 256;
        int r = idx >> 4;
        int f4 = (idx & 15) * 4;
        float4 qv = *(const float4*)(Qb + (size_t)(q0 + r) * DM + f4);
        Qs[f4 + 0][r] = qv.x; Qs[f4 + 1][r] = qv.y;
        Qs[f4 + 2][r] = qv.z; Qs[f4 + 3][r] = qv.w;
        float4 kv = *(const float4*)(Kb + (size_t)(s0 + r) * DM + f4);
        Ks[f4 + 0][r] = kv.x; Ks[f4 + 1][r] = kv.y;
        Ks[f4 + 2][r] = kv.z; Ks[f4 + 3][r] = kv.w;
    }
    __syncthreads();
    int tx = tid & 15, ty = tid >> 4;
    float acc[4][4] = {};
#pragma unroll
    for (int k = 0; k < 64; k++) {
        float a[4], bb[4];
        *(float4*)a  = *(const float4*)&Qs[k][ty * 4];
        *(float4*)bb = *(const float4*)&Ks[k][tx * 4];
#pragma unroll
        for (int i = 0; i < 4; i++)
#pragma unroll
            for (int j = 0; j < 4; j++)
                acc[i][j] = fmaf(a[i], bb[j], acc[i][j]);
    }
    float* Sout = g_S + (size_t)bh * TT * TT;
#pragma unroll
    for (int i = 0; i < 4; i++)
#pragma unroll
        for (int j = 0; j < 4; j++)
            Sout[(size_t)(q0 + ty * 4 + i) * TT + s0 + tx * 4 + j] = acc[i][j] * 0.125f;
}

// ---------------- column softmax stats (over q axis!) ---------------------------
__global__ void __launch_bounds__(256) softmax_stats() {
    int bh = blockIdx.y;
    int s = blockIdx.x * 256 + threadIdx.x;
    const float* Sb = g_S + (size_t)bh * TT * TT + s;
    float m = -3.4e38f;
#pragma unroll 8
    for (int q = 0; q < TT; q++) m = fmaxf(m, Sb[(size_t)q * TT]);
    float z = 0.f;
#pragma unroll 8
    for (int q = 0; q < TT; q++) z += __expf(Sb[(size_t)q * TT] - m);
    g_m[bh * TT + s] = m;
    g_zinv[bh * TT + s] = 1.f / z;
}

// ---------------- part[q,v] = sum_s softmaxQ(S)[q,s] * V[s,v] (rounded out) -----
__global__ void __launch_bounds__(256) av_kernel() {
    int bh = blockIdx.y;
    int b = bh >> 4, h = bh & 15;
    int q0 = blockIdx.x * 64;
    __shared__ float As[32][68];
    __shared__ float Vs[32][64];
    const float* Sb = g_S + (size_t)bh * TT * TT;
    const float* Vb = g_V + (size_t)(b * TT) * DM + h * DKK;
    const float* mb = g_m + bh * TT;
    const float* zb = g_zinv + bh * TT;
    int tid = threadIdx.x, tx = tid & 15, ty = tid >> 4;
    float acc[4][4] = {};
    for (int s0 = 0; s0 < TT; s0 += 32) {
        __syncthreads();
#pragma unroll
        for (int j = 0; j < 2; j++) {
            int idx = tid + j * 256;
            int q = idx >> 3, f4 = (idx & 7) * 4;
            float4 sv = *(const float4*)(Sb + (size_t)(q0 + q) * TT + s0 + f4);
            As[f4 + 0][q] = __expf(sv.x - mb[s0 + f4 + 0]) * zb[s0 + f4 + 0];
            As[f4 + 1][q] = __expf(sv.y - mb[s0 + f4 + 1]) * zb[s0 + f4 + 1];
            As[f4 + 2][q] = __expf(sv.z - mb[s0 + f4 + 2]) * zb[s0 + f4 + 2];
            As[f4 + 3][q] = __expf(sv.w - mb[s0 + f4 + 3]) * zb[s0 + f4 + 3];
            int sv2 = idx >> 4, vf = (idx & 15) * 4;
            *(float4*)&Vs[sv2][vf] = *(const float4*)(Vb + (size_t)(s0 + sv2) * DM + vf);
        }
        __syncthreads();
#pragma unroll
        for (int ss = 0; ss < 32; ss++) {
            float a[4], vv[4];
            *(float4*)a  = *(const float4*)&As[ss][ty * 4];
            *(float4*)vv = *(const float4*)&Vs[ss][tx * 4];
#pragma unroll
            for (int i = 0; i < 4; i++)
#pragma unroll
                for (int j = 0; j < 4; j++)
                    acc[i][j] = fmaf(a[i], vv[j], acc[i][j]);
        }
    }
#pragma unroll
    for (int i = 0; i < 4; i++)
#pragma unroll
        for (int j = 0; j < 4; j++)
            g_part[(size_t)(b * TT + q0 + ty * 4 + i) * DM + h * DKK + tx * 4 + j]
                = rtf(acc[i][j]);
}

// ---------------- pseudo-norm: y - mean - std(ddof=1) ---------------------------
template <bool ROUND>
__global__ void __launch_bounds__(256) pnorm_kernel(const float* __restrict__ in,
                                                    float* __restrict__ out) {
    int row = blockIdx.x;
    const float* p = in + (size_t)row * DM;
    float s = 0.f, s2 = 0.f;
    for (int i = threadIdx.x; i < DM; i += 256) {
        float v = p[i];
        s += v;
        s2 = fmaf(v, v, s2);
    }
    __shared__ float sh[2][8];
#pragma unroll
    for (int o = 16; o > 0; o >>= 1) {
        s  += __shfl_down_sync(0xffffffffu, s, o);
        s2 += __shfl_down_sync(0xffffffffu, s2, o);
    }
    int wid = threadIdx.x >> 5, lane = threadIdx.x & 31;
    if (lane == 0) { sh[0][wid] = s; sh[1][wid] = s2; }
    __syncthreads();
    __shared__ float bsub;
    if (threadIdx.x == 0) {
        float ts = 0.f, ts2 = 0.f;
#pragma unroll
        for (int i = 0; i < 8; i++) { ts += sh[0][i]; ts2 += sh[1][i]; }
        float mean = ts * (1.f / 1024.f);
        float var = (ts2 - 1024.f * mean * mean) * (1.f / 1023.f);
        bsub = mean + sqrtf(fmaxf(var, 0.f));
    }
    __syncthreads();
    float sub = bsub;
    for (int i = threadIdx.x; i < DM; i += 256) {
        float v = p[i] - sub;
        out[(size_t)row * DM + i] = ROUND ? rtf(v) : v;
    }
}

// ---------------- launch --------------------------------------------------------
extern "C" void kernel_launch(void* const* d_in, const int* in_sizes, int n_in,
                              void* d_out, int out_size) {
    const float* x  = (const float*)d_in[0];
    const float* Wq = (const float*)d_in[1];
    const float* Wk = (const float*)d_in[2];
    const float* Wv = (const float*)d_in[3];
    const float* Wo = (const float*)d_in[4];
    const float* W1 = (const float*)d_in[5];
    const float* b1 = (const float*)d_in[6];
    const float* W2 = (const float*)d_in[7];
    const float* b2 = (const float*)d_in[8];
    float* out = (float*)d_out;

    float *pXr, *pWqr, *pWkr, *pWvr, *pWor, *pW1r, *pW2r;
    float *pQ, *pK, *pV, *pPart, *pOut1, *pFfh, *pOut2;
    cudaGetSymbolAddress((void**)&pXr,   g_xr);
    cudaGetSymbolAddress((void**)&pWqr,  g_Wqr);
    cudaGetSymbolAddress((void**)&pWkr,  g_Wkr);
    cudaGetSymbolAddress((void**)&pWvr,  g_Wvr);
    cudaGetSymbolAddress((void**)&pWor,  g_Wor);
    cudaGetSymbolAddress((void**)&pW1r,  g_W1r);
    cudaGetSymbolAddress((void**)&pW2r,  g_W2r);
    cudaGetSymbolAddress((void**)&pQ,    g_Q);
    cudaGetSymbolAddress((void**)&pK,    g_K);
    cudaGetSymbolAddress((void**)&pV,    g_V);
    cudaGetSymbolAddress((void**)&pPart, g_part);
    cudaGetSymbolAddress((void**)&pOut1, g_out1);
    cudaGetSymbolAddress((void**)&pFfh,  g_ffh);
    cudaGetSymbolAddress((void**)&pOut2, g_out2);

    cudaFuncSetAttribute(gemm_mma<0>, cudaFuncAttributeMaxDynamicSharedMemorySize, GM_SMEM_BYTES);
    cudaFuncSetAttribute(gemm_mma<1>, cudaFuncAttributeMaxDynamicSharedMemorySize, GM_SMEM_BYTES);
    cudaFuncSetAttribute(gemm_mma<2>, cudaFuncAttributeMaxDynamicSharedMemorySize, GM_SMEM_BYTES);
    cudaFuncSetAttribute(gemm_mma<3>, cudaFuncAttributeMaxDynamicSharedMemorySize, GM_SMEM_BYTES);

    // operand rounding / repacks
    round_x<<<BT * DM / 256, 256>>>(x);
    repack_qkv<<<DM * DM / 256, 256>>>(Wq, Wk, Wv);
    repack_wo<<<DM * DM / 256, 256>>>(Wo);
    repack_w12<<<FFI * DM / 256, 256>>>(W1, W2);

    // QKV projections: [8192,1024] x [1024,1024]^T(K-major)
    dim3 gq(DM / 128, BT / 128);
    gemm_mma<0><<<gq, 256, GM_SMEM_BYTES>>>(pXr, DM, pWqr, DM, pQ, DM, DM, nullptr, nullptr, 0);
    gemm_mma<0><<<gq, 256, GM_SMEM_BYTES>>>(pXr, DM, pWkr, DM, pK, DM, DM, nullptr, nullptr, 0);
    gemm_mma<0><<<gq, 256, GM_SMEM_BYTES>>>(pXr, DM, pWvr, DM, pV, DM, DM, nullptr, nullptr, 0);

    // attention (SIMT, fp32)
    scores_kernel<<<dim3(16, 16, BHN), 256>>>();
    softmax_stats<<<dim3(TT / 256, BHN), 256>>>();
    av_kernel<<<dim3(TT / 64, BHN), 256>>>();

    // Wo projection + residual (res = ORIGINAL x), then pseudo-norm (rounded out)
    gemm_mma<1><<<gq, 256, GM_SMEM_BYTES>>>(pPart, DM, pWor, DM, pOut1, DM, DM, nullptr, x, DM);
    pnorm_kernel<true><<<BT, 256>>>(pOut1, pOut1);

    // FF
    dim3 gff(FFI / 128, BT / 128);
    gemm_mma<2><<<gff, 256, GM_SMEM_BYTES>>>(pOut1, DM, pW1r, DM, pFfh, FFI, DM, b1, nullptr, 0);
    gemm_mma<3><<<gq, 256, GM_SMEM_BYTES>>>(pFfh, FFI, pW2r, FFI, pOut2, DM, FFI, b2, pOut1, DM);

    // final pseudo-norm -> output (NOT rounded)
    pnorm_kernel<false><<<BT, 256>>>(pOut2, out);
}

// round 4
// speedup vs baseline: 3.5603x; 1.5734x over previous
#include <cuda_runtime.h>
#include <cstdint>
#include <math.h>

#define BQ   8
#define TT   1024
#define DM   1024
#define NH   16
#define DKK  64
#define FFI  4096
#define BT   (BQ*TT)   // 8192 rows
#define BHN  (BQ*NH)   // 128 (b,h) pairs
#define QKVN 3072

// ---------------- scratch (static device globals) --------------------------------
__device__ float g_xr[BT*DM];               // tf32-rounded x
__device__ float g_Wqkv[QKVN*DM];           // [n][k]; n<1024:Wq*c, <2048:Wk, else Wv (rounded)
__device__ float g_Wor[DM*DM];              // [n][k] = Wo^T, rounded
__device__ float g_W1r[FFI*DM];
__device__ float g_W2r[DM*FFI];
__device__ float g_QKV[(size_t)BT*QKVN];    // [bt][3072] rounded (Q prescaled by log2e/8)
__device__ float g_S[(size_t)BHN*TT*TT];    // P = rtf(exp(S)) unnormalized, 512 MB
__device__ float g_zpart[BHN*8*TT];         // per-qblock column partial sums
__device__ float g_zinv[BHN*TT];
__device__ float g_Vt[(size_t)BHN*DKK*TT];  // V'[bh][v][s] = rtf(V*zinv), 32 MB
__device__ float g_part[BT*DM];             // rounded
__device__ float g_out1[BT*DM];
__device__ float g_ffh[(size_t)BT*FFI];
__device__ float g_out2[BT*DM];

// ================= helpers =======================================================
__device__ __forceinline__ uint32_t smem_to_u32(const void* p) {
    uint32_t a;
    asm("{ .reg .u64 t; cvta.to.shared.u64 t, %1; cvt.u32.u64 %0, t; }" : "=r"(a) : "l"(p));
    return a;
}
__device__ __forceinline__ float rtf(float f) {
    uint32_t u;
    asm("cvt.rna.tf32.f32 %0, %1;" : "=r"(u) : "f"(f));
    return __uint_as_float(u);
}
__device__ __forceinline__ float ex2f(float x) {
    float r;
    asm("ex2.approx.f32 %0, %1;" : "=f"(r) : "f"(x));
    return r;
}
__device__ __forceinline__ void cpasync16(uint32_t dst, const void* src) {
    asm volatile("cp.async.cg.shared.global [%0], [%1], 16;" :: "r"(dst), "l"(src));
}
#define CP_COMMIT() asm volatile("cp.async.commit_group;" ::: "memory")
#define CP_WAIT(n)  asm volatile("cp.async.wait_group %0;" :: "n"(n) : "memory")

__device__ __forceinline__ void mma_tf32(float* c, uint32_t a0, uint32_t a1,
                                         uint32_t a2, uint32_t a3,
                                         uint32_t b0, uint32_t b1) {
    asm volatile(
        "mma.sync.aligned.m16n8k8.row.col.f32.tf32.tf32.f32 "
        "{%0,%1,%2,%3}, {%4,%5,%6,%7}, {%8,%9}, {%0,%1,%2,%3};"
        : "+f"(c[0]), "+f"(c[1]), "+f"(c[2]), "+f"(c[3])
        : "r"(a0), "r"(a1), "r"(a2), "r"(a3), "r"(b0), "r"(b1));
}

// ================= dense GEMM: C[M,N] = A[M,K]*B[N,K]^T (+epi) ==================
// Block 128x128, 8 warps (2x4), K-step 32, cp.async double buffer, pitch 36.
// EPI: 0 none, 1 +res, 2 relu(+bias)+round, 3 +bias+res, 4 round
#define GM_SMEM_BYTES 73728

template <int EPI>
__global__ void __launch_bounds__(256, 2) gemm_mma(
    const float* __restrict__ A, int lda,
    const float* __restrict__ B, int ldb,
    float* __restrict__ C, int ldc,
    int K,
    const float* __restrict__ bias,
    const float* __restrict__ res, int ldres)
{
    extern __shared__ uint32_t smem[];
    const int tid = threadIdx.x;
    const int wid = tid >> 5, lane = tid & 31;
    const int wm = wid >> 2, wn = wid & 3;
    const int grp = lane >> 2, kq = lane & 3;
    const int m0 = blockIdx.y * 128, n0 = blockIdx.x * 128;

    const float* Ab = A + (size_t)m0 * lda;
    const float* Bb = B + (size_t)n0 * ldb;
    const uint32_t sbase = smem_to_u32(smem);

    float acc[4][4][4] = {};
    const int NC = K / 32;
    const int lr = tid >> 3, lc = (tid & 7) * 4;

    auto issue = [&](int c, int buf) {
        const int k0 = c * 32;
        const uint32_t sA = sbase + buf * 36864u;
        const uint32_t sB = sA + 18432u;
#pragma unroll
        for (int j = 0; j < 4; j++) {
            int rr = lr + j * 32;
            cpasync16(sA + rr * 144u + lc * 4u, Ab + (size_t)rr * lda + k0 + lc);
            cpasync16(sB + rr * 144u + lc * 4u, Bb + (size_t)rr * ldb + k0 + lc);
        }
    };

    issue(0, 0);
    CP_COMMIT();

    for (int c = 0; c < NC; c++) {
        const int buf = c & 1;
        if (c + 1 < NC) { issue(c + 1, buf ^ 1); CP_COMMIT(); CP_WAIT(1); }
        else            { CP_WAIT(0); }
        __syncthreads();
        const uint32_t* As = smem + buf * 9216;
        const uint32_t* Bs = As + 4608;
#pragma unroll
        for (int ks = 0; ks < 4; ks++) {
            const int k0 = ks * 8;
            uint32_t bf[4][2];
#pragma unroll
            for (int ni = 0; ni < 4; ni++) {
                int nrow = wn * 32 + ni * 8 + grp;
                bf[ni][0] = Bs[nrow * 36 + k0 + kq];
                bf[ni][1] = Bs[nrow * 36 + k0 + kq + 4];
            }
#pragma unroll
            for (int mi = 0; mi < 4; mi++) {
                int mrow = wm * 64 + mi * 16 + grp;
                uint32_t a0 = As[mrow * 36 + k0 + kq];
                uint32_t a1 = As[(mrow + 8) * 36 + k0 + kq];
                uint32_t a2 = As[mrow * 36 + k0 + kq + 4];
                uint32_t a3 = As[(mrow + 8) * 36 + k0 + kq + 4];
#pragma unroll
                for (int ni = 0; ni < 4; ni++)
                    mma_tf32(acc[mi][ni], a0, a1, a2, a3, bf[ni][0], bf[ni][1]);
            }
        }
        __syncthreads();
    }

#pragma unroll
    for (int mi = 0; mi < 4; mi++) {
        int row = m0 + wm * 64 + mi * 16 + grp;
#pragma unroll
        for (int ni = 0; ni < 4; ni++) {
            int col = n0 + wn * 32 + ni * 8 + kq * 2;
            float v00 = acc[mi][ni][0], v01 = acc[mi][ni][1];
            float v10 = acc[mi][ni][2], v11 = acc[mi][ni][3];
            if (EPI == 1 || EPI == 3) {
                float2 r0 = *(const float2*)(res + (size_t)row * ldres + col);
                float2 r1 = *(const float2*)(res + (size_t)(row + 8) * ldres + col);
                v00 += r0.x; v01 += r0.y; v10 += r1.x; v11 += r1.y;
            }
            if (EPI == 2) {
                float b0 = bias[col], b1 = bias[col + 1];
                v00 = rtf(fmaxf(v00 + b0, 0.f)); v01 = rtf(fmaxf(v01 + b1, 0.f));
                v10 = rtf(fmaxf(v10 + b0, 0.f)); v11 = rtf(fmaxf(v11 + b1, 0.f));
            }
            if (EPI == 3) {
                float b0 = bias[col], b1 = bias[col + 1];
                v00 += b0; v01 += b1; v10 += b0; v11 += b1;
            }
            if (EPI == 4) { v00 = rtf(v00); v01 = rtf(v01); v10 = rtf(v10); v11 = rtf(v11); }
            float2 o0 = {v00, v01}, o1 = {v10, v11};
            *(float2*)(C + (size_t)row * ldc + col) = o0;
            *(float2*)(C + (size_t)(row + 8) * ldc + col) = o1;
        }
    }
}

// ===== scores: P = rtf(exp2(Q'·K^T)), column partial sums per q-block ============
// Q' prescaled by log2e/8. Block 128q x 128s, K=64. Tiles: 2 chunks of 32, pitch 36.
#define SC_SMEM_BYTES (73728 + 1024)

__global__ void __launch_bounds__(256, 2) scores_mma() {
    extern __shared__ uint32_t smem[];
    const int tid = threadIdx.x;
    const int wid = tid >> 5, lane = tid & 31;
    const int wm = wid >> 2, wn = wid & 3;
    const int grp = lane >> 2, kq = lane & 3;
    const int bh = blockIdx.z, b = bh >> 4, h = bh & 15;
    const int q0 = blockIdx.y * 128, s0 = blockIdx.x * 128;

    const float* Ab = g_QKV + (size_t)(b * TT + q0) * QKVN + h * DKK;          // Q'
    const float* Bb = g_QKV + (size_t)(b * TT + s0) * QKVN + 1024 + h * DKK;   // K
    const uint32_t sbase = smem_to_u32(smem);
    const uint32_t sB0 = sbase + 36864u;

    // load 128x64 tiles (2 chunks of 32 cols each, pitch 36 words)
    {
        const int r = tid >> 4;             // 0..15
        const int c4 = tid & 15;            // f4 index 0..15
        const int chunk = c4 >> 3, cc = c4 & 7;
#pragma unroll
        for (int j = 0; j < 8; j++) {
            int rr = r + j * 16;
            uint32_t off = chunk * 18432u + rr * 144u + cc * 16u;
            cpasync16(sbase + off, Ab + (size_t)rr * QKVN + c4 * 4);
            cpasync16(sB0 + off, Bb + (size_t)rr * QKVN + c4 * 4);
        }
    }
    CP_COMMIT(); CP_WAIT(0);
    __syncthreads();

    float acc[4][4][4] = {};
    const uint32_t* As = smem;
    const uint32_t* Bs = smem + 9216;
#pragma unroll
    for (int ks = 0; ks < 8; ks++) {
        const int cofs = (ks >> 2) * 4608 + (ks & 3) * 8;
        uint32_t bf[4][2];
#pragma unroll
        for (int ni = 0; ni < 4; ni++) {
            int nrow = wn * 32 + ni * 8 + grp;
            bf[ni][0] = Bs[cofs + nrow * 36 + kq];
            bf[ni][1] = Bs[cofs + nrow * 36 + kq + 4];
        }
#pragma unroll
        for (int mi = 0; mi < 4; mi++) {
            int mrow = wm * 64 + mi * 16 + grp;
            uint32_t a0 = As[cofs + mrow * 36 + kq];
            uint32_t a1 = As[cofs + (mrow + 8) * 36 + kq];
            uint32_t a2 = As[cofs + mrow * 36 + kq + 4];
            uint32_t a3 = As[cofs + (mrow + 8) * 36 + kq + 4];
#pragma unroll
            for (int ni = 0; ni < 4; ni++)
                mma_tf32(acc[mi][ni], a0, a1, a2, a3, bf[ni][0], bf[ni][1]);
        }
    }
    __syncthreads();

    // epilogue: P = rtf(ex2(acc)), store + column partials
    float* zsm = (float*)(smem + 18432);    // [2][128]
    float* Sb = g_S + (size_t)bh * TT * TT;
    float cs0[4] = {}, cs1[4] = {};
#pragma unroll
    for (int mi = 0; mi < 4; mi++) {
        int row = q0 + wm * 64 + mi * 16 + grp;
#pragma unroll
        for (int ni = 0; ni < 4; ni++) {
            int col = s0 + wn * 32 + ni * 8 + kq * 2;
            float p00 = rtf(ex2f(acc[mi][ni][0]));
            float p01 = rtf(ex2f(acc[mi][ni][1]));
            float p10 = rtf(ex2f(acc[mi][ni][2]));
            float p11 = rtf(ex2f(acc[mi][ni][3]));
            cs0[ni] += p00 + p10;
            cs1[ni] += p01 + p11;
            float2 o0 = {p00, p01}, o1 = {p10, p11};
            *(float2*)(Sb + (size_t)row * TT + col) = o0;
            *(float2*)(Sb + (size_t)(row + 8) * TT + col) = o1;
        }
    }
#pragma unroll
    for (int ni = 0; ni < 4; ni++) {
#pragma unroll
        for (int o = 16; o >= 4; o >>= 1) {
            cs0[ni] += __shfl_down_sync(0xffffffffu, cs0[ni], o);
            cs1[ni] += __shfl_down_sync(0xffffffffu, cs1[ni], o);
        }
        if (grp == 0) {
            int c = wn * 32 + ni * 8 + kq * 2;
            zsm[wm * 128 + c] = cs0[ni];
            zsm[wm * 128 + c + 1] = cs1[ni];
        }
    }
    __syncthreads();
    if (tid < 128)
        g_zpart[(bh * 8 + blockIdx.y) * TT + s0 + tid] = zsm[tid] + zsm[128 + tid];
}

// ===== zinv reduce ================================================================
__global__ void __launch_bounds__(256) zinv_kernel() {
    int bh = blockIdx.x;
#pragma unroll
    for (int j = 0; j < 4; j++) {
        int s = threadIdx.x + j * 256;
        float z = 0.f;
#pragma unroll
        for (int q = 0; q < 8; q++) z += g_zpart[(bh * 8 + q) * TT + s];
        g_zinv[bh * TT + s] = 1.f / z;
    }
}

// ===== V' transpose: g_Vt[bh][v][s] = rtf(V[b,s,h,v]*zinv[bh,s]) =================
__global__ void __launch_bounds__(256) vz_kernel() {
    __shared__ float sm[64][132];
    int bh = blockIdx.y, b = bh >> 4, h = bh & 15;
    int s0 = blockIdx.x * 128;
    const float* Vb = g_QKV + (size_t)(b * TT + s0) * QKVN + 2048 + h * DKK;
    const float* zb = g_zinv + bh * TT + s0;
    int tid = threadIdx.x;
#pragma unroll
    for (int t = 0; t < 8; t++) {
        int f4i = tid + t * 256;
        int r = f4i >> 4, c4 = (f4i & 15) * 4;
        float4 v = *(const float4*)(Vb + (size_t)r * QKVN + c4);
        float zi = zb[r];
        sm[c4 + 0][r] = rtf(v.x * zi);
        sm[c4 + 1][r] = rtf(v.y * zi);
        sm[c4 + 2][r] = rtf(v.z * zi);
        sm[c4 + 3][r] = rtf(v.w * zi);
    }
    __syncthreads();
    float* Vt = g_Vt + (size_t)bh * DKK * TT;
#pragma unroll
    for (int t = 0; t < 8; t++) {
        int i = tid + t * 256;
        int v = i >> 5, s4 = (i & 31) * 4;
        float4 o = {sm[v][s4], sm[v][s4 + 1], sm[v][s4 + 2], sm[v][s4 + 3]};
        *(float4*)(Vt + (size_t)v * TT + s0 + s4) = o;
    }
}

// ===== AV GEMM: part[q][h*64+v] = sum_s P[q,s] * V'[v,s] =========================
// Block 128(M) x 64(N), 8 warps (4x2), warp 32x32, K-step 32, double buffer.
#define AV_SMEM_BYTES 55296

__global__ void __launch_bounds__(256, 2) av_mma() {
    extern __shared__ uint32_t smem[];
    const int tid = threadIdx.x;
    const int wid = tid >> 5, lane = tid & 31;
    const int wm = wid >> 1, wn = wid & 1;
    const int grp = lane >> 2, kq = lane & 3;
    const int bh = blockIdx.y, b = bh >> 4, h = bh & 15;
    const int m0 = blockIdx.x * 128;

    const float* Ab = g_S + (size_t)bh * TT * TT + (size_t)m0 * TT;
    const float* Bb = g_Vt + (size_t)bh * DKK * TT;
    const uint32_t sbase = smem_to_u32(smem);

    float acc[2][4][4] = {};
    const int lr = tid >> 3, lc = (tid & 7) * 4;

    auto issue = [&](int c, int buf) {
        const int k0 = c * 32;
        const uint32_t sA = sbase + buf * 27648u;
        const uint32_t sB = sA + 18432u;
#pragma unroll
        for (int j = 0; j < 4; j++) {
            int rr = lr + j * 32;
            cpasync16(sA + rr * 144u + lc * 4u, Ab + (size_t)rr * TT + k0 + lc);
        }
#pragma unroll
        for (int j = 0; j < 2; j++) {
            int rr = lr + j * 32;
            cpasync16(sB + rr * 144u + lc * 4u, Bb + (size_t)rr * TT + k0 + lc);
        }
    };

    issue(0, 0);
    CP_COMMIT();

    for (int c = 0; c < 32; c++) {
        const int buf = c & 1;
        if (c + 1 < 32) { issue(c + 1, buf ^ 1); CP_COMMIT(); CP_WAIT(1); }
        else            { CP_WAIT(0); }
        __syncthreads();
        const uint32_t* As = smem + buf * 6912;
        const uint32_t* Bs = As + 4608;
#pragma unroll
        for (int ks = 0; ks < 4; ks++) {
            const int k0 = ks * 8;
            uint32_t bf[4][2];
#pragma unroll
            for (int ni = 0; ni < 4; ni++) {
                int nrow = wn * 32 + ni * 8 + grp;
                bf[ni][0] = Bs[nrow * 36 + k0 + kq];
                bf[ni][1] = Bs[nrow * 36 + k0 + kq + 4];
            }
#pragma unroll
            for (int mi = 0; mi < 2; mi++) {
                int mrow = wm * 32 + mi * 16 + grp;
                uint32_t a0 = As[mrow * 36 + k0 + kq];
                uint32_t a1 = As[(mrow + 8) * 36 + k0 + kq];
                uint32_t a2 = As[mrow * 36 + k0 + kq + 4];
                uint32_t a3 = As[(mrow + 8) * 36 + k0 + kq + 4];
#pragma unroll
                for (int ni = 0; ni < 4; ni++)
                    mma_tf32(acc[mi][ni], a0, a1, a2, a3, bf[ni][0], bf[ni][1]);
            }
        }
        __syncthreads();
    }

#pragma unroll
    for (int mi = 0; mi < 2; mi++) {
        int row = b * TT + m0 + wm * 32 + mi * 16 + grp;
#pragma unroll
        for (int ni = 0; ni < 4; ni++) {
            int col = h * DKK + wn * 32 + ni * 8 + kq * 2;
            float2 o0 = {rtf(acc[mi][ni][0]), rtf(acc[mi][ni][1])};
            float2 o1 = {rtf(acc[mi][ni][2]), rtf(acc[mi][ni][3])};
            *(float2*)(g_part + (size_t)row * DM + col) = o0;
            *(float2*)(g_part + (size_t)(row + 8) * DM + col) = o1;
        }
    }
}

// ---------------- producers / repacks --------------------------------------------
__global__ void __launch_bounds__(256) round_x(const float* __restrict__ x) {
    int i = blockIdx.x * 256 + threadIdx.x;
    g_xr[i] = rtf(x[i]);
}
__global__ void __launch_bounds__(256) repack_qkv3(const float* __restrict__ Wq,
                                                   const float* __restrict__ Wk,
                                                   const float* __restrict__ Wv) {
    const float QSCALE = 0.125f * 1.4426950408889634f;   // (1/8)*log2(e)
    int i = blockIdx.x * 256 + threadIdx.x;   // i = n*1024 + d, n in [0,3072)
    int n = i >> 10, d = i & 1023;
    int hh = (n & 1023) >> 6, kk = n & 63;
    int src = (hh * DM + d) * DKK + kk;
    float v;
    if (n < 1024)      v = Wq[src] * QSCALE;
    else if (n < 2048) v = Wk[src];
    else               v = Wv[src];
    g_Wqkv[i] = rtf(v);
}
__global__ void __launch_bounds__(256) repack_wo(const float* __restrict__ Wo) {
    int i = blockIdx.x * 256 + threadIdx.x;
    int n = i >> 10, k = i & 1023;
    g_Wor[i] = rtf(Wo[k * DM + n]);
}
__global__ void __launch_bounds__(256) repack_w12(const float* __restrict__ W1,
                                                  const float* __restrict__ W2) {
    int i = blockIdx.x * 256 + threadIdx.x;
    g_W1r[i] = rtf(W1[i]);
    g_W2r[i] = rtf(W2[i]);
}

// ---------------- pseudo-norm ----------------------------------------------------
template <bool ROUND>
__global__ void __launch_bounds__(256) pnorm_kernel(const float* __restrict__ in,
                                                    float* __restrict__ out) {
    int row = blockIdx.x;
    const float* p = in + (size_t)row * DM;
    float s = 0.f, s2 = 0.f;
    for (int i = threadIdx.x; i < DM; i += 256) {
        float v = p[i];
        s += v;
        s2 = fmaf(v, v, s2);
    }
    __shared__ float sh[2][8];
#pragma unroll
    for (int o = 16; o > 0; o >>= 1) {
        s  += __shfl_down_sync(0xffffffffu, s, o);
        s2 += __shfl_down_sync(0xffffffffu, s2, o);
    }
    int wid = threadIdx.x >> 5, lane = threadIdx.x & 31;
    if (lane == 0) { sh[0][wid] = s; sh[1][wid] = s2; }
    __syncthreads();
    __shared__ float bsub;
    if (threadIdx.x == 0) {
        float ts = 0.f, ts2 = 0.f;
#pragma unroll
        for (int i = 0; i < 8; i++) { ts += sh[0][i]; ts2 += sh[1][i]; }
        float mean = ts * (1.f / 1024.f);
        float var = (ts2 - 1024.f * mean * mean) * (1.f / 1023.f);
        bsub = mean + sqrtf(fmaxf(var, 0.f));
    }
    __syncthreads();
    float sub = bsub;
    for (int i = threadIdx.x; i < DM; i += 256) {
        float v = p[i] - sub;
        out[(size_t)row * DM + i] = ROUND ? rtf(v) : v;
    }
}

// ---------------- launch ----------------------------------------------------------
extern "C" void kernel_launch(void* const* d_in, const int* in_sizes, int n_in,
                              void* d_out, int out_size) {
    const float* x  = (const float*)d_in[0];
    const float* Wq = (const float*)d_in[1];
    const float* Wk = (const float*)d_in[2];
    const float* Wv = (const float*)d_in[3];
    const float* Wo = (const float*)d_in[4];
    const float* W1 = (const float*)d_in[5];
    const float* b1 = (const float*)d_in[6];
    const float* W2 = (const float*)d_in[7];
    const float* b2 = (const float*)d_in[8];
    float* out = (float*)d_out;

    float *pXr, *pWqkv, *pWor, *pW1r, *pW2r, *pQKV, *pPart, *pOut1, *pFfh, *pOut2;
    cudaGetSymbolAddress((void**)&pXr,   g_xr);
    cudaGetSymbolAddress((void**)&pWqkv, g_Wqkv);
    cudaGetSymbolAddress((void**)&pWor,  g_Wor);
    cudaGetSymbolAddress((void**)&pW1r,  g_W1r);
    cudaGetSymbolAddress((void**)&pW2r,  g_W2r);
    cudaGetSymbolAddress((void**)&pQKV,  g_QKV);
    cudaGetSymbolAddress((void**)&pPart, g_part);
    cudaGetSymbolAddress((void**)&pOut1, g_out1);
    cudaGetSymbolAddress((void**)&pFfh,  g_ffh);
    cudaGetSymbolAddress((void**)&pOut2, g_out2);

    cudaFuncSetAttribute(gemm_mma<0>, cudaFuncAttributeMaxDynamicSharedMemorySize, GM_SMEM_BYTES);
    cudaFuncSetAttribute(gemm_mma<1>, cudaFuncAttributeMaxDynamicSharedMemorySize, GM_SMEM_BYTES);
    cudaFuncSetAttribute(gemm_mma<2>, cudaFuncAttributeMaxDynamicSharedMemorySize, GM_SMEM_BYTES);
    cudaFuncSetAttribute(gemm_mma<3>, cudaFuncAttributeMaxDynamicSharedMemorySize, GM_SMEM_BYTES);
    cudaFuncSetAttribute(gemm_mma<4>, cudaFuncAttributeMaxDynamicSharedMemorySize, GM_SMEM_BYTES);
    cudaFuncSetAttribute(scores_mma,  cudaFuncAttributeMaxDynamicSharedMemorySize, SC_SMEM_BYTES);
    cudaFuncSetAttribute(av_mma,      cudaFuncAttributeMaxDynamicSharedMemorySize, AV_SMEM_BYTES);

    // producers
    round_x<<<BT * DM / 256, 256>>>(x);
    repack_qkv3<<<QKVN * DM / 256, 256>>>(Wq, Wk, Wv);
    repack_wo<<<DM * DM / 256, 256>>>(Wo);
    repack_w12<<<FFI * DM / 256, 256>>>(W1, W2);

    // fused QKV projection: [8192,1024] x [3072,1024]^T, rounded epilogue
    gemm_mma<4><<<dim3(QKVN / 128, BT / 128), 256, GM_SMEM_BYTES>>>(
        pXr, DM, pWqkv, DM, pQKV, QKVN, DM, nullptr, nullptr, 0);

    // attention
    scores_mma<<<dim3(8, 8, BHN), 256, SC_SMEM_BYTES>>>();
    zinv_kernel<<<BHN, 256>>>();
    vz_kernel<<<dim3(8, BHN), 256>>>();
    av_mma<<<dim3(8, BHN), 256, AV_SMEM_BYTES>>>();

    // Wo + residual, pseudo-norm (rounded)
    dim3 gq(DM / 128, BT / 128);
    gemm_mma<1><<<gq, 256, GM_SMEM_BYTES>>>(pPart, DM, pWor, DM, pOut1, DM, DM, nullptr, x, DM);
    pnorm_kernel<true><<<BT, 256>>>(pOut1, pOut1);

    // FF
    dim3 gff(FFI / 128, BT / 128);
    gemm_mma<2><<<gff, 256, GM_SMEM_BYTES>>>(pOut1, DM, pW1r, DM, pFfh, FFI, DM, b1, nullptr, 0);
    gemm_mma<3><<<gq, 256, GM_SMEM_BYTES>>>(pFfh, FFI, pW2r, FFI, pOut2, DM, FFI, b2, pOut1, DM);

    // final pseudo-norm -> output
    pnorm_kernel<false><<<BT, 256>>>(pOut2, out);
}

// round 5
// speedup vs baseline: 4.3802x; 1.2303x over previous
#include <cuda_runtime.h>
#include <cuda_bf16.h>
#include <cstdint>
#include <math.h>

#define BQ   8
#define TT   1024
#define DM   1024
#define NH   16
#define DKK  64
#define FFI  4096
#define BT   (BQ*TT)   // 8192 rows
#define BHN  (BQ*NH)   // 128 (b,h) pairs
#define QKVN 3072

// ---------------- scratch (static device globals) --------------------------------
__device__ __nv_bfloat16 g_xh[BT*DM];                 // x in bf16
__device__ __nv_bfloat16 g_Wqkvh[QKVN*DM];            // [n][k] bf16 (Q cols prescaled)
__device__ __nv_bfloat16 g_Worh[DM*DM];               // Wo^T bf16
__device__ __nv_bfloat16 g_QKVh[(size_t)BT*QKVN];     // QKV bf16
__device__ __nv_bfloat16 g_Sh[(size_t)BHN*TT*TT];     // P bf16 (256 MB)
__device__ __nv_bfloat16 g_Vth[(size_t)BHN*DKK*TT];   // V'[bh][v][s] bf16
__device__ __nv_bfloat16 g_parth[BT*DM];              // attention out bf16
__device__ float g_W1r[FFI*DM];                       // tf32-rounded
__device__ float g_W2r[DM*FFI];
__device__ float g_zpart[BHN*8*TT];
__device__ float g_zinv[BHN*TT];
__device__ float g_out1[BT*DM];
__device__ float g_ffh[(size_t)BT*FFI];
__device__ float g_out2[BT*DM];

// ================= helpers =======================================================
__device__ __forceinline__ uint32_t smem_to_u32(const void* p) {
    uint32_t a;
    asm("{ .reg .u64 t; cvta.to.shared.u64 t, %1; cvt.u32.u64 %0, t; }" : "=r"(a) : "l"(p));
    return a;
}
__device__ __forceinline__ float rtf(float f) {
    uint32_t u;
    asm("cvt.rna.tf32.f32 %0, %1;" : "=r"(u) : "f"(f));
    return __uint_as_float(u);
}
__device__ __forceinline__ float ex2f(float x) {
    float r;
    asm("ex2.approx.f32 %0, %1;" : "=f"(r) : "f"(x));
    return r;
}
__device__ __forceinline__ uint32_t pack_bf162(float lo, float hi) {
    uint32_t r;
    asm("cvt.rn.bf16x2.f32 %0, %1, %2;" : "=r"(r) : "f"(hi), "f"(lo));
    return r;
}
__device__ __forceinline__ void cpasync16(uint32_t dst, const void* src) {
    asm volatile("cp.async.cg.shared.global [%0], [%1], 16;" :: "r"(dst), "l"(src));
}
#define CP_COMMIT() asm volatile("cp.async.commit_group;" ::: "memory")
#define CP_WAIT(n)  asm volatile("cp.async.wait_group %0;" :: "n"(n) : "memory")

__device__ __forceinline__ void mma_tf32(float* c, uint32_t a0, uint32_t a1,
                                         uint32_t a2, uint32_t a3,
                                         uint32_t b0, uint32_t b1) {
    asm volatile(
        "mma.sync.aligned.m16n8k8.row.col.f32.tf32.tf32.f32 "
        "{%0,%1,%2,%3}, {%4,%5,%6,%7}, {%8,%9}, {%0,%1,%2,%3};"
        : "+f"(c[0]), "+f"(c[1]), "+f"(c[2]), "+f"(c[3])
        : "r"(a0), "r"(a1), "r"(a2), "r"(a3), "r"(b0), "r"(b1));
}
__device__ __forceinline__ void mma_bf16(float* c, uint32_t a0, uint32_t a1,
                                         uint32_t a2, uint32_t a3,
                                         uint32_t b0, uint32_t b1) {
    asm volatile(
        "mma.sync.aligned.m16n8k16.row.col.f32.bf16.bf16.f32 "
        "{%0,%1,%2,%3}, {%4,%5,%6,%7}, {%8,%9}, {%0,%1,%2,%3};"
        : "+f"(c[0]), "+f"(c[1]), "+f"(c[2]), "+f"(c[3])
        : "r"(a0), "r"(a1), "r"(a2), "r"(a3), "r"(b0), "r"(b1));
}

// ================= tf32 dense GEMM (FF path only) ================================
// Block 128x128, 8 warps (2x4), K-step 32, cp.async double buffer, pitch 36 words.
// EPI: 2 relu(+bias)+round, 3 +bias+res
#define GM_SMEM_BYTES 73728

template <int EPI>
__global__ void __launch_bounds__(256, 2) gemm_mma(
    const float* __restrict__ A, int lda,
    const float* __restrict__ B, int ldb,
    float* __restrict__ C, int ldc,
    int K,
    const float* __restrict__ bias,
    const float* __restrict__ res, int ldres)
{
    extern __shared__ uint32_t smem[];
    const int tid = threadIdx.x;
    const int wid = tid >> 5, lane = tid & 31;
    const int wm = wid >> 2, wn = wid & 3;
    const int grp = lane >> 2, kq = lane & 3;
    const int m0 = blockIdx.y * 128, n0 = blockIdx.x * 128;

    const float* Ab = A + (size_t)m0 * lda;
    const float* Bb = B + (size_t)n0 * ldb;
    const uint32_t sbase = smem_to_u32(smem);

    float acc[4][4][4] = {};
    const int NC = K / 32;
    const int lr = tid >> 3, lc = (tid & 7) * 4;

    auto issue = [&](int c, int buf) {
        const int k0 = c * 32;
        const uint32_t sA = sbase + buf * 36864u;
        const uint32_t sB = sA + 18432u;
#pragma unroll
        for (int j = 0; j < 4; j++) {
            int rr = lr + j * 32;
            cpasync16(sA + rr * 144u + lc * 4u, Ab + (size_t)rr * lda + k0 + lc);
            cpasync16(sB + rr * 144u + lc * 4u, Bb + (size_t)rr * ldb + k0 + lc);
        }
    };

    issue(0, 0);
    CP_COMMIT();

    for (int c = 0; c < NC; c++) {
        const int buf = c & 1;
        if (c + 1 < NC) { issue(c + 1, buf ^ 1); CP_COMMIT(); CP_WAIT(1); }
        else            { CP_WAIT(0); }
        __syncthreads();
        const uint32_t* As = smem + buf * 9216;
        const uint32_t* Bs = As + 4608;
#pragma unroll
        for (int ks = 0; ks < 4; ks++) {
            const int k0 = ks * 8;
            uint32_t bf[4][2];
#pragma unroll
            for (int ni = 0; ni < 4; ni++) {
                int nrow = wn * 32 + ni * 8 + grp;
                bf[ni][0] = Bs[nrow * 36 + k0 + kq];
                bf[ni][1] = Bs[nrow * 36 + k0 + kq + 4];
            }
#pragma unroll
            for (int mi = 0; mi < 4; mi++) {
                int mrow = wm * 64 + mi * 16 + grp;
                uint32_t a0 = As[mrow * 36 + k0 + kq];
                uint32_t a1 = As[(mrow + 8) * 36 + k0 + kq];
                uint32_t a2 = As[mrow * 36 + k0 + kq + 4];
                uint32_t a3 = As[(mrow + 8) * 36 + k0 + kq + 4];
#pragma unroll
                for (int ni = 0; ni < 4; ni++)
                    mma_tf32(acc[mi][ni], a0, a1, a2, a3, bf[ni][0], bf[ni][1]);
            }
        }
        __syncthreads();
    }

#pragma unroll
    for (int mi = 0; mi < 4; mi++) {
        int row = m0 + wm * 64 + mi * 16 + grp;
#pragma unroll
        for (int ni = 0; ni < 4; ni++) {
            int col = n0 + wn * 32 + ni * 8 + kq * 2;
            float v00 = acc[mi][ni][0], v01 = acc[mi][ni][1];
            float v10 = acc[mi][ni][2], v11 = acc[mi][ni][3];
            if (EPI == 2) {
                float b0 = bias[col], b1 = bias[col + 1];
                v00 = rtf(fmaxf(v00 + b0, 0.f)); v01 = rtf(fmaxf(v01 + b1, 0.f));
                v10 = rtf(fmaxf(v10 + b0, 0.f)); v11 = rtf(fmaxf(v11 + b1, 0.f));
            }
            if (EPI == 3) {
                float2 r0 = *(const float2*)(res + (size_t)row * ldres + col);
                float2 r1 = *(const float2*)(res + (size_t)(row + 8) * ldres + col);
                float b0 = bias[col], b1 = bias[col + 1];
                v00 += b0 + r0.x; v01 += b1 + r0.y;
                v10 += b0 + r1.x; v11 += b1 + r1.y;
            }
            float2 o0 = {v00, v01}, o1 = {v10, v11};
            *(float2*)(C + (size_t)row * ldc + col) = o0;
            *(float2*)(C + (size_t)(row + 8) * ldc + col) = o1;
        }
    }
}

// ================= bf16 dense GEMM: C[M,N] = A[M,K]*B[N,K]^T =====================
// Block 128x128, 8 warps (2x4), K-step 64 (128B rows), double buffer, pitch 144B.
// EPI: 4 -> bf16 C out;  1 -> fp32 C = acc + res
template <int EPI>
__global__ void __launch_bounds__(256, 2) gemm_bf(
    const __nv_bfloat16* __restrict__ A, int lda,
    const __nv_bfloat16* __restrict__ B, int ldb,
    void* __restrict__ Cv, int ldc,
    int K,
    const float* __restrict__ res, int ldres)
{
    extern __shared__ uint32_t smem[];
    const int tid = threadIdx.x;
    const int wid = tid >> 5, lane = tid & 31;
    const int wm = wid >> 2, wn = wid & 3;
    const int grp = lane >> 2, kq = lane & 3;
    const int m0 = blockIdx.y * 128, n0 = blockIdx.x * 128;

    const __nv_bfloat16* Ab = A + (size_t)m0 * lda;
    const __nv_bfloat16* Bb = B + (size_t)n0 * ldb;
    const uint32_t sbase = smem_to_u32(smem);

    float acc[4][4][4] = {};
    const int NC = K / 64;
    const int lr = tid >> 3, lseg = tid & 7;

    auto issue = [&](int c, int buf) {
        const int k0 = c * 64;
        const uint32_t sA = sbase + buf * 36864u;
        const uint32_t sB = sA + 18432u;
#pragma unroll
        for (int j = 0; j < 4; j++) {
            int rr = lr + j * 32;
            cpasync16(sA + rr * 144u + lseg * 16u, Ab + (size_t)rr * lda + k0 + lseg * 8);
            cpasync16(sB + rr * 144u + lseg * 16u, Bb + (size_t)rr * ldb + k0 + lseg * 8);
        }
    };

    issue(0, 0);
    CP_COMMIT();

    for (int c = 0; c < NC; c++) {
        const int buf = c & 1;
        if (c + 1 < NC) { issue(c + 1, buf ^ 1); CP_COMMIT(); CP_WAIT(1); }
        else            { CP_WAIT(0); }
        __syncthreads();
        const uint32_t* As = smem + buf * 9216;
        const uint32_t* Bs = As + 4608;
#pragma unroll
        for (int ks = 0; ks < 4; ks++) {
            const int k0 = ks * 8;
            uint32_t bf[4][2];
#pragma unroll
            for (int ni = 0; ni < 4; ni++) {
                int nrow = wn * 32 + ni * 8 + grp;
                bf[ni][0] = Bs[nrow * 36 + k0 + kq];
                bf[ni][1] = Bs[nrow * 36 + k0 + kq + 4];
            }
#pragma unroll
            for (int mi = 0; mi < 4; mi++) {
                int mrow = wm * 64 + mi * 16 + grp;
                uint32_t a0 = As[mrow * 36 + k0 + kq];
                uint32_t a1 = As[(mrow + 8) * 36 + k0 + kq];
                uint32_t a2 = As[mrow * 36 + k0 + kq + 4];
                uint32_t a3 = As[(mrow + 8) * 36 + k0 + kq + 4];
#pragma unroll
                for (int ni = 0; ni < 4; ni++)
                    mma_bf16(acc[mi][ni], a0, a1, a2, a3, bf[ni][0], bf[ni][1]);
            }
        }
        __syncthreads();
    }

#pragma unroll
    for (int mi = 0; mi < 4; mi++) {
        int row = m0 + wm * 64 + mi * 16 + grp;
#pragma unroll
        for (int ni = 0; ni < 4; ni++) {
            int col = n0 + wn * 32 + ni * 8 + kq * 2;
            if (EPI == 4) {
                __nv_bfloat16* C = (__nv_bfloat16*)Cv;
                uint32_t o0 = pack_bf162(acc[mi][ni][0], acc[mi][ni][1]);
                uint32_t o1 = pack_bf162(acc[mi][ni][2], acc[mi][ni][3]);
                *(uint32_t*)(C + (size_t)row * ldc + col) = o0;
                *(uint32_t*)(C + (size_t)(row + 8) * ldc + col) = o1;
            } else {
                float* C = (float*)Cv;
                float2 r0 = *(const float2*)(res + (size_t)row * ldres + col);
                float2 r1 = *(const float2*)(res + (size_t)(row + 8) * ldres + col);
                float2 o0 = {acc[mi][ni][0] + r0.x, acc[mi][ni][1] + r0.y};
                float2 o1 = {acc[mi][ni][2] + r1.x, acc[mi][ni][3] + r1.y};
                *(float2*)(C + (size_t)row * ldc + col) = o0;
                *(float2*)(C + (size_t)(row + 8) * ldc + col) = o1;
            }
        }
    }
}

// ===== scores: P = bf16(exp2(Q'·K^T)), column partial sums per q-block ===========
// Q' prescaled by log2e/8 (bf16). Block 128q x 128s, K=64 (single chunk).
#define SC_SMEM_BYTES (36864 + 1024)

__global__ void __launch_bounds__(256, 2) scores_bf() {
    extern __shared__ uint32_t smem[];
    const int tid = threadIdx.x;
    const int wid = tid >> 5, lane = tid & 31;
    const int wm = wid >> 2, wn = wid & 3;
    const int grp = lane >> 2, kq = lane & 3;
    const int bh = blockIdx.z, b = bh >> 4, h = bh & 15;
    const int q0 = blockIdx.y * 128, s0 = blockIdx.x * 128;

    const __nv_bfloat16* Ab = g_QKVh + (size_t)(b * TT + q0) * QKVN + h * DKK;
    const __nv_bfloat16* Bb = g_QKVh + (size_t)(b * TT + s0) * QKVN + 1024 + h * DKK;
    const uint32_t sbase = smem_to_u32(smem);
    const uint32_t sB0 = sbase + 18432u;

    // 128 rows x 64 halves (128B) per tile
#pragma unroll
    for (int j = 0; j < 4; j++) {
        int idx = tid + j * 256;
        int rr = idx >> 3, seg = idx & 7;
        cpasync16(sbase + rr * 144u + seg * 16u, Ab + (size_t)rr * QKVN + seg * 8);
        cpasync16(sB0 + rr * 144u + seg * 16u, Bb + (size_t)rr * QKVN + seg * 8);
    }
    CP_COMMIT(); CP_WAIT(0);
    __syncthreads();

    float acc[4][4][4] = {};
    const uint32_t* As = smem;
    const uint32_t* Bs = smem + 4608;
#pragma unroll
    for (int ks = 0; ks < 4; ks++) {
        const int k0 = ks * 8;
        uint32_t bf[4][2];
#pragma unroll
        for (int ni = 0; ni < 4; ni++) {
            int nrow = wn * 32 + ni * 8 + grp;
            bf[ni][0] = Bs[nrow * 36 + k0 + kq];
            bf[ni][1] = Bs[nrow * 36 + k0 + kq + 4];
        }
#pragma unroll
        for (int mi = 0; mi < 4; mi++) {
            int mrow = wm * 64 + mi * 16 + grp;
            uint32_t a0 = As[mrow * 36 + k0 + kq];
            uint32_t a1 = As[(mrow + 8) * 36 + k0 + kq];
            uint32_t a2 = As[mrow * 36 + k0 + kq + 4];
            uint32_t a3 = As[(mrow + 8) * 36 + k0 + kq + 4];
#pragma unroll
            for (int ni = 0; ni < 4; ni++)
                mma_bf16(acc[mi][ni], a0, a1, a2, a3, bf[ni][0], bf[ni][1]);
        }
    }
    __syncthreads();

    float* zsm = (float*)(smem + 9216);   // [2][128]
    __nv_bfloat16* Sb = g_Sh + (size_t)bh * TT * TT;
    float cs0[4] = {}, cs1[4] = {};
#pragma unroll
    for (int mi = 0; mi < 4; mi++) {
        int row = q0 + wm * 64 + mi * 16 + grp;
#pragma unroll
        for (int ni = 0; ni < 4; ni++) {
            int col = s0 + wn * 32 + ni * 8 + kq * 2;
            float p00 = ex2f(acc[mi][ni][0]);
            float p01 = ex2f(acc[mi][ni][1]);
            float p10 = ex2f(acc[mi][ni][2]);
            float p11 = ex2f(acc[mi][ni][3]);
            cs0[ni] += p00 + p10;
            cs1[ni] += p01 + p11;
            *(uint32_t*)(Sb + (size_t)row * TT + col) = pack_bf162(p00, p01);
            *(uint32_t*)(Sb + (size_t)(row + 8) * TT + col) = pack_bf162(p10, p11);
        }
    }
#pragma unroll
    for (int ni = 0; ni < 4; ni++) {
#pragma unroll
        for (int o = 16; o >= 4; o >>= 1) {
            cs0[ni] += __shfl_down_sync(0xffffffffu, cs0[ni], o);
            cs1[ni] += __shfl_down_sync(0xffffffffu, cs1[ni], o);
        }
        if (grp == 0) {
            int c = wn * 32 + ni * 8 + kq * 2;
            zsm[wm * 128 + c] = cs0[ni];
            zsm[wm * 128 + c + 1] = cs1[ni];
        }
    }
    __syncthreads();
    if (tid < 128)
        g_zpart[(bh * 8 + blockIdx.y) * TT + s0 + tid] = zsm[tid] + zsm[128 + tid];
}

// ===== zinv reduce ================================================================
__global__ void __launch_bounds__(256) zinv_kernel() {
    int bh = blockIdx.x;
#pragma unroll
    for (int j = 0; j < 4; j++) {
        int s = threadIdx.x + j * 256;
        float z = 0.f;
#pragma unroll
        for (int q = 0; q < 8; q++) z += g_zpart[(bh * 8 + q) * TT + s];
        g_zinv[bh * TT + s] = 1.f / z;
    }
}

// ===== V' transpose: g_Vth[bh][v][s] = bf16(V[b,s,h,v]*zinv[bh,s]) ===============
__global__ void __launch_bounds__(256) vz_kernel() {
    __shared__ float sm[64][132];
    int bh = blockIdx.y, b = bh >> 4, h = bh & 15;
    int s0 = blockIdx.x * 128;
    const __nv_bfloat16* Vb = g_QKVh + (size_t)(b * TT + s0) * QKVN + 2048 + h * DKK;
    const float* zb = g_zinv + bh * TT + s0;
    int tid = threadIdx.x;
    // 128 s-rows x 64 v (32 half2 per row)
#pragma unroll
    for (int t = 0; t < 16; t++) {
        int idx = tid + t * 256;                 // over 128*32 half2 units
        int r = idx >> 5, c2 = (idx & 31) * 2;
        __nv_bfloat162 v2 = *(const __nv_bfloat162*)(Vb + (size_t)r * QKVN + c2);
        float2 vf = __bfloat1622float2(v2);
        float zi = zb[r];
        sm[c2 + 0][r] = vf.x * zi;
        sm[c2 + 1][r] = vf.y * zi;
    }
    __syncthreads();
    __nv_bfloat16* Vt = g_Vth + (size_t)bh * DKK * TT + s0;
#pragma unroll
    for (int t = 0; t < 16; t++) {
        int idx = tid + t * 256;                 // over 64*64 half2 units
        int v = idx >> 6, s2 = (idx & 63) * 2;
        *(uint32_t*)(Vt + (size_t)v * TT + s2) = pack_bf162(sm[v][s2], sm[v][s2 + 1]);
    }
}

// ===== AV GEMM (bf16): part[q][h*64+v] = sum_s P[q,s] * V'[v,s] ==================
// Block 128(M) x 64(N), 8 warps (4x2), K-step 64, double buffer.
#define AV_SMEM_BYTES 55296

__global__ void __launch_bounds__(256, 2) av_bf() {
    extern __shared__ uint32_t smem[];
    const int tid = threadIdx.x;
    const int wid = tid >> 5, lane = tid & 31;
    const int wm = wid >> 1, wn = wid & 1;
    const int grp = lane >> 2, kq = lane & 3;
    const int bh = blockIdx.y, b = bh >> 4, h = bh & 15;
    const int m0 = blockIdx.x * 128;

    const __nv_bfloat16* Ab = g_Sh + (size_t)bh * TT * TT + (size_t)m0 * TT;
    const __nv_bfloat16* Bb = g_Vth + (size_t)bh * DKK * TT;
    const uint32_t sbase = smem_to_u32(smem);

    float acc[2][4][4] = {};
    const int lr = tid >> 3, lseg = tid & 7;

    auto issue = [&](int c, int buf) {
        const int k0 = c * 64;
        const uint32_t sA = sbase + buf * 27648u;
        const uint32_t sB = sA + 18432u;
#pragma unroll
        for (int j = 0; j < 4; j++) {
            int rr = lr + j * 32;
            cpasync16(sA + rr * 144u + lseg * 16u, Ab + (size_t)rr * TT + k0 + lseg * 8);
        }
#pragma unroll
        for (int j = 0; j < 2; j++) {
            int rr = lr + j * 32;
            cpasync16(sB + rr * 144u + lseg * 16u, Bb + (size_t)rr * TT + k0 + lseg * 8);
        }
    };

    issue(0, 0);
    CP_COMMIT();

    for (int c = 0; c < 16; c++) {
        const int buf = c & 1;
        if (c + 1 < 16) { issue(c + 1, buf ^ 1); CP_COMMIT(); CP_WAIT(1); }
        else            { CP_WAIT(0); }
        __syncthreads();
        const uint32_t* As = smem + buf * 6912;
        const uint32_t* Bs = As + 4608;
#pragma unroll
        for (int ks = 0; ks < 4; ks++) {
            const int k0 = ks * 8;
            uint32_t bf[4][2];
#pragma unroll
            for (int ni = 0; ni < 4; ni++) {
                int nrow = wn * 32 + ni * 8 + grp;
                bf[ni][0] = Bs[nrow * 36 + k0 + kq];
                bf[ni][1] = Bs[nrow * 36 + k0 + kq + 4];
            }
#pragma unroll
            for (int mi = 0; mi < 2; mi++) {
                int mrow = wm * 32 + mi * 16 + grp;
                uint32_t a0 = As[mrow * 36 + k0 + kq];
                uint32_t a1 = As[(mrow + 8) * 36 + k0 + kq];
                uint32_t a2 = As[mrow * 36 + k0 + kq + 4];
                uint32_t a3 = As[(mrow + 8) * 36 + k0 + kq + 4];
#pragma unroll
                for (int ni = 0; ni < 4; ni++)
                    mma_bf16(acc[mi][ni], a0, a1, a2, a3, bf[ni][0], bf[ni][1]);
            }
        }
        __syncthreads();
    }

#pragma unroll
    for (int mi = 0; mi < 2; mi++) {
        int row = b * TT + m0 + wm * 32 + mi * 16 + grp;
#pragma unroll
        for (int ni = 0; ni < 4; ni++) {
            int col = h * DKK + wn * 32 + ni * 8 + kq * 2;
            *(uint32_t*)(g_parth + (size_t)row * DM + col)
                = pack_bf162(acc[mi][ni][0], acc[mi][ni][1]);
            *(uint32_t*)(g_parth + (size_t)(row + 8) * DM + col)
                = pack_bf162(acc[mi][ni][2], acc[mi][ni][3]);
        }
    }
}

// ---------------- producers / repacks --------------------------------------------
__global__ void __launch_bounds__(256) round_xh(const float* __restrict__ x) {
    int i = blockIdx.x * 256 + threadIdx.x;
    g_xh[i] = __float2bfloat16(x[i]);
}
__global__ void __launch_bounds__(256) repack_qkv3h(const float* __restrict__ Wq,
                                                    const float* __restrict__ Wk,
                                                    const float* __restrict__ Wv) {
    const float QSCALE = 0.125f * 1.4426950408889634f;   // (1/8)*log2(e)
    int i = blockIdx.x * 256 + threadIdx.x;   // i = n*1024 + d
    int n = i >> 10, d = i & 1023;
    int hh = (n & 1023) >> 6, kk = n & 63;
    int src = (hh * DM + d) * DKK + kk;
    float v;
    if (n < 1024)      v = Wq[src] * QSCALE;
    else if (n < 2048) v = Wk[src];
    else               v = Wv[src];
    g_Wqkvh[i] = __float2bfloat16(v);
}
__global__ void __launch_bounds__(256) repack_woh(const float* __restrict__ Wo) {
    int i = blockIdx.x * 256 + threadIdx.x;
    int n = i >> 10, k = i & 1023;
    g_Worh[i] = __float2bfloat16(Wo[k * DM + n]);
}
__global__ void __launch_bounds__(256) repack_w12(const float* __restrict__ W1,
                                                  const float* __restrict__ W2) {
    int i = blockIdx.x * 256 + threadIdx.x;
    g_W1r[i] = rtf(W1[i]);
    g_W2r[i] = rtf(W2[i]);
}

// ---------------- pseudo-norm ----------------------------------------------------
template <bool ROUND>
__global__ void __launch_bounds__(256) pnorm_kernel(const float* __restrict__ in,
                                                    float* __restrict__ out) {
    int row = blockIdx.x;
    const float* p = in + (size_t)row * DM;
    float s = 0.f, s2 = 0.f;
    for (int i = threadIdx.x; i < DM; i += 256) {
        float v = p[i];
        s += v;
        s2 = fmaf(v, v, s2);
    }
    __shared__ float sh[2][8];
#pragma unroll
    for (int o = 16; o > 0; o >>= 1) {
        s  += __shfl_down_sync(0xffffffffu, s, o);
        s2 += __shfl_down_sync(0xffffffffu, s2, o);
    }
    int wid = threadIdx.x >> 5, lane = threadIdx.x & 31;
    if (lane == 0) { sh[0][wid] = s; sh[1][wid] = s2; }
    __syncthreads();
    __shared__ float bsub;
    if (threadIdx.x == 0) {
        float ts = 0.f, ts2 = 0.f;
#pragma unroll
        for (int i = 0; i < 8; i++) { ts += sh[0][i]; ts2 += sh[1][i]; }
        float mean = ts * (1.f / 1024.f);
        float var = (ts2 - 1024.f * mean * mean) * (1.f / 1023.f);
        bsub = mean + sqrtf(fmaxf(var, 0.f));
    }
    __syncthreads();
    float sub = bsub;
    for (int i = threadIdx.x; i < DM; i += 256) {
        float v = p[i] - sub;
        out[(size_t)row * DM + i] = ROUND ? rtf(v) : v;
    }
}

// ---------------- launch ----------------------------------------------------------
extern "C" void kernel_launch(void* const* d_in, const int* in_sizes, int n_in,
                              void* d_out, int out_size) {
    const float* x  = (const float*)d_in[0];
    const float* Wq = (const float*)d_in[1];
    const float* Wk = (const float*)d_in[2];
    const float* Wv = (const float*)d_in[3];
    const float* Wo = (const float*)d_in[4];
    const float* W1 = (const float*)d_in[5];
    const float* b1 = (const float*)d_in[6];
    const float* W2 = (const float*)d_in[7];
    const float* b2 = (const float*)d_in[8];
    float* out = (float*)d_out;

    __nv_bfloat16 *pXh, *pWqkvh, *pWorh, *pQKVh, *pParth;
    float *pW1r, *pW2r, *pOut1, *pFfh, *pOut2;
    cudaGetSymbolAddress((void**)&pXh,    g_xh);
    cudaGetSymbolAddress((void**)&pWqkvh, g_Wqkvh);
    cudaGetSymbolAddress((void**)&pWorh,  g_Worh);
    cudaGetSymbolAddress((void**)&pQKVh,  g_QKVh);
    cudaGetSymbolAddress((void**)&pParth, g_parth);
    cudaGetSymbolAddress((void**)&pW1r,   g_W1r);
    cudaGetSymbolAddress((void**)&pW2r,   g_W2r);
    cudaGetSymbolAddress((void**)&pOut1,  g_out1);
    cudaGetSymbolAddress((void**)&pFfh,   g_ffh);
    cudaGetSymbolAddress((void**)&pOut2,  g_out2);

    cudaFuncSetAttribute(gemm_mma<2>, cudaFuncAttributeMaxDynamicSharedMemorySize, GM_SMEM_BYTES);
    cudaFuncSetAttribute(gemm_mma<3>, cudaFuncAttributeMaxDynamicSharedMemorySize, GM_SMEM_BYTES);
    cudaFuncSetAttribute(gemm_bf<1>,  cudaFuncAttributeMaxDynamicSharedMemorySize, GM_SMEM_BYTES);
    cudaFuncSetAttribute(gemm_bf<4>,  cudaFuncAttributeMaxDynamicSharedMemorySize, GM_SMEM_BYTES);
    cudaFuncSetAttribute(scores_bf,   cudaFuncAttributeMaxDynamicSharedMemorySize, SC_SMEM_BYTES);
    cudaFuncSetAttribute(av_bf,       cudaFuncAttributeMaxDynamicSharedMemorySize, AV_SMEM_BYTES);

    // producers
    round_xh<<<BT * DM / 256, 256>>>(x);
    repack_qkv3h<<<QKVN * DM / 256, 256>>>(Wq, Wk, Wv);
    repack_woh<<<DM * DM / 256, 256>>>(Wo);
    repack_w12<<<FFI * DM / 256, 256>>>(W1, W2);

    // fused QKV projection (bf16): [8192,1024] x [3072,1024]^T -> bf16
    gemm_bf<4><<<dim3(QKVN / 128, BT / 128), 256, GM_SMEM_BYTES>>>(
        pXh, DM, pWqkvh, DM, pQKVh, QKVN, DM, nullptr, 0);

    // attention (bf16)
    scores_bf<<<dim3(8, 8, BHN), 256, SC_SMEM_BYTES>>>();
    zinv_kernel<<<BHN, 256>>>();
    vz_kernel<<<dim3(8, BHN), 256>>>();
    av_bf<<<dim3(8, BHN), 256, AV_SMEM_BYTES>>>();

    // Wo (bf16) + residual (fp32 x), then pseudo-norm (tf32-rounded out)
    gemm_bf<1><<<dim3(DM / 128, BT / 128), 256, GM_SMEM_BYTES>>>(
        pParth, DM, pWorh, DM, pOut1, DM, DM, x, DM);
    pnorm_kernel<true><<<BT, 256>>>(pOut1, pOut1);

    // FF (tf32)
    dim3 gq(DM / 128, BT / 128);
    dim3 gff(FFI / 128, BT / 128);
    gemm_mma<2><<<gff, 256, GM_SMEM_BYTES>>>(pOut1, DM, pW1r, DM, pFfh, FFI, DM, b1, nullptr, 0);
    gemm_mma<3><<<gq, 256, GM_SMEM_BYTES>>>(pFfh, FFI, pW2r, FFI, pOut2, DM, FFI, b2, pOut1, DM);

    // final pseudo-norm -> output
    pnorm_kernel<false><<<BT, 256>>>(pOut2, out);
}

// round 6
// speedup vs baseline: 6.1476x; 1.4035x over previous
#include <cuda_runtime.h>
#include <cuda_bf16.h>
#include <cuda_fp16.h>
#include <cstdint>
#include <math.h>

#define BQ   8
#define TT   1024
#define DM   1024
#define NH   16
#define DKK  64
#define FFI  4096
#define BT   (BQ*TT)   // 8192 rows
#define BHN  (BQ*NH)   // 128 (b,h) pairs
#define QKVN 3072

// ---------------- scratch (static device globals) --------------------------------
__device__ __nv_bfloat16 g_xh[BT*DM];                 // x in bf16
__device__ __nv_bfloat16 g_Wqkvh[QKVN*DM];            // [n][k] bf16 (Q cols prescaled)
__device__ __nv_bfloat16 g_Worh[DM*DM];               // Wo^T bf16
__device__ __nv_bfloat16 g_QKVh[(size_t)BT*QKVN];     // QKV bf16
__device__ __nv_bfloat16 g_Sh[(size_t)BHN*TT*TT];     // P bf16 (256 MB)
__device__ __nv_bfloat16 g_Vth[(size_t)BHN*DKK*TT];   // V'[bh][v][s] bf16
__device__ __nv_bfloat16 g_parth[BT*DM];              // attention out bf16
__device__ __half g_W1h[FFI*DM];                      // W1 fp16 [f][d]
__device__ __half g_W2h[DM*FFI];                      // W2 fp16 [d][f]
__device__ __half g_out1h[BT*DM];                     // out1 fp16 (GEMM A)
__device__ __half g_ffhh[(size_t)BT*FFI];             // FF hidden fp16
__device__ float g_zpart[BHN*8*TT];
__device__ float g_zinv[BHN*TT];
__device__ float g_out1[BT*DM];                       // out1 fp32 (residual)
__device__ float g_out2[BT*DM];

// ================= helpers =======================================================
__device__ __forceinline__ uint32_t smem_to_u32(const void* p) {
    uint32_t a;
    asm("{ .reg .u64 t; cvta.to.shared.u64 t, %1; cvt.u32.u64 %0, t; }" : "=r"(a) : "l"(p));
    return a;
}
__device__ __forceinline__ float ex2f(float x) {
    float r;
    asm("ex2.approx.f32 %0, %1;" : "=f"(r) : "f"(x));
    return r;
}
__device__ __forceinline__ uint32_t pack_bf162(float lo, float hi) {
    uint32_t r;
    asm("cvt.rn.bf16x2.f32 %0, %1, %2;" : "=r"(r) : "f"(hi), "f"(lo));
    return r;
}
__device__ __forceinline__ uint32_t pack_f162(float lo, float hi) {
    uint32_t r;
    asm("cvt.rn.f16x2.f32 %0, %1, %2;" : "=r"(r) : "f"(hi), "f"(lo));
    return r;
}
__device__ __forceinline__ void cpasync16(uint32_t dst, const void* src) {
    asm volatile("cp.async.cg.shared.global [%0], [%1], 16;" :: "r"(dst), "l"(src));
}
#define CP_COMMIT() asm volatile("cp.async.commit_group;" ::: "memory")
#define CP_WAIT(n)  asm volatile("cp.async.wait_group %0;" :: "n"(n) : "memory")

__device__ __forceinline__ void mma_bf16(float* c, uint32_t a0, uint32_t a1,
                                         uint32_t a2, uint32_t a3,
                                         uint32_t b0, uint32_t b1) {
    asm volatile(
        "mma.sync.aligned.m16n8k16.row.col.f32.bf16.bf16.f32 "
        "{%0,%1,%2,%3}, {%4,%5,%6,%7}, {%8,%9}, {%0,%1,%2,%3};"
        : "+f"(c[0]), "+f"(c[1]), "+f"(c[2]), "+f"(c[3])
        : "r"(a0), "r"(a1), "r"(a2), "r"(a3), "r"(b0), "r"(b1));
}
__device__ __forceinline__ void mma_fp16(float* c, uint32_t a0, uint32_t a1,
                                         uint32_t a2, uint32_t a3,
                                         uint32_t b0, uint32_t b1) {
    asm volatile(
        "mma.sync.aligned.m16n8k16.row.col.f32.f16.f16.f32 "
        "{%0,%1,%2,%3}, {%4,%5,%6,%7}, {%8,%9}, {%0,%1,%2,%3};"
        : "+f"(c[0]), "+f"(c[1]), "+f"(c[2]), "+f"(c[3])
        : "r"(a0), "r"(a1), "r"(a2), "r"(a3), "r"(b0), "r"(b1));
}

// ================= half-precision dense GEMM =====================================
// C[M,N] = A[M,K]*B[N,K]^T. Block 128x128, 8 warps (2x4), K-step 64, double buffer.
// FMT: 0 = bf16 operands, 1 = fp16 operands.
// EPI: 4 -> half C out (raw)
//      1 -> fp32 C = acc + res
//      2 -> half C = relu(acc + bias)
//      3 -> fp32 C = acc + bias + res
#define GM_SMEM_BYTES 73728

template <int EPI, int FMT>
__global__ void __launch_bounds__(256, 2) gemm_h(
    const void* __restrict__ Av, int lda,
    const void* __restrict__ Bv, int ldb,
    void* __restrict__ Cv, int ldc,
    int K,
    const float* __restrict__ bias,
    const float* __restrict__ res, int ldres)
{
    extern __shared__ uint32_t smem[];
    const int tid = threadIdx.x;
    const int wid = tid >> 5, lane = tid & 31;
    const int wm = wid >> 2, wn = wid & 3;
    const int grp = lane >> 2, kq = lane & 3;
    const int m0 = blockIdx.y * 128, n0 = blockIdx.x * 128;

    const uint16_t* Ab = (const uint16_t*)Av + (size_t)m0 * lda;
    const uint16_t* Bb = (const uint16_t*)Bv + (size_t)n0 * ldb;
    const uint32_t sbase = smem_to_u32(smem);

    float acc[4][4][4] = {};
    const int NC = K / 64;
    const int lr = tid >> 3, lseg = tid & 7;

    auto issue = [&](int c, int buf) {
        const int k0 = c * 64;
        const uint32_t sA = sbase + buf * 36864u;
        const uint32_t sB = sA + 18432u;
#pragma unroll
        for (int j = 0; j < 4; j++) {
            int rr = lr + j * 32;
            cpasync16(sA + rr * 144u + lseg * 16u, Ab + (size_t)rr * lda + k0 + lseg * 8);
            cpasync16(sB + rr * 144u + lseg * 16u, Bb + (size_t)rr * ldb + k0 + lseg * 8);
        }
    };

    issue(0, 0);
    CP_COMMIT();

    for (int c = 0; c < NC; c++) {
        const int buf = c & 1;
        if (c + 1 < NC) { issue(c + 1, buf ^ 1); CP_COMMIT(); CP_WAIT(1); }
        else            { CP_WAIT(0); }
        __syncthreads();
        const uint32_t* As = smem + buf * 9216;
        const uint32_t* Bs = As + 4608;
#pragma unroll
        for (int ks = 0; ks < 4; ks++) {
            const int k0 = ks * 8;
            uint32_t bf[4][2];
#pragma unroll
            for (int ni = 0; ni < 4; ni++) {
                int nrow = wn * 32 + ni * 8 + grp;
                bf[ni][0] = Bs[nrow * 36 + k0 + kq];
                bf[ni][1] = Bs[nrow * 36 + k0 + kq + 4];
            }
#pragma unroll
            for (int mi = 0; mi < 4; mi++) {
                int mrow = wm * 64 + mi * 16 + grp;
                uint32_t a0 = As[mrow * 36 + k0 + kq];
                uint32_t a1 = As[(mrow + 8) * 36 + k0 + kq];
                uint32_t a2 = As[mrow * 36 + k0 + kq + 4];
                uint32_t a3 = As[(mrow + 8) * 36 + k0 + kq + 4];
#pragma unroll
                for (int ni = 0; ni < 4; ni++) {
                    if (FMT == 0) mma_bf16(acc[mi][ni], a0, a1, a2, a3, bf[ni][0], bf[ni][1]);
                    else          mma_fp16(acc[mi][ni], a0, a1, a2, a3, bf[ni][0], bf[ni][1]);
                }
            }
        }
        __syncthreads();
    }

#pragma unroll
    for (int mi = 0; mi < 4; mi++) {
        int row = m0 + wm * 64 + mi * 16 + grp;
#pragma unroll
        for (int ni = 0; ni < 4; ni++) {
            int col = n0 + wn * 32 + ni * 8 + kq * 2;
            float v00 = acc[mi][ni][0], v01 = acc[mi][ni][1];
            float v10 = acc[mi][ni][2], v11 = acc[mi][ni][3];
            if (EPI == 4) {
                uint16_t* C = (uint16_t*)Cv;
                uint32_t o0 = FMT ? pack_f162(v00, v01) : pack_bf162(v00, v01);
                uint32_t o1 = FMT ? pack_f162(v10, v11) : pack_bf162(v10, v11);
                *(uint32_t*)(C + (size_t)row * ldc + col) = o0;
                *(uint32_t*)(C + (size_t)(row + 8) * ldc + col) = o1;
            } else if (EPI == 2) {
                uint16_t* C = (uint16_t*)Cv;
                float b0 = bias[col], b1 = bias[col + 1];
                v00 = fmaxf(v00 + b0, 0.f); v01 = fmaxf(v01 + b1, 0.f);
                v10 = fmaxf(v10 + b0, 0.f); v11 = fmaxf(v11 + b1, 0.f);
                uint32_t o0 = FMT ? pack_f162(v00, v01) : pack_bf162(v00, v01);
                uint32_t o1 = FMT ? pack_f162(v10, v11) : pack_bf162(v10, v11);
                *(uint32_t*)(C + (size_t)row * ldc + col) = o0;
                *(uint32_t*)(C + (size_t)(row + 8) * ldc + col) = o1;
            } else {
                float* C = (float*)Cv;
                float2 r0 = *(const float2*)(res + (size_t)row * ldres + col);
                float2 r1 = *(const float2*)(res + (size_t)(row + 8) * ldres + col);
                if (EPI == 3) {
                    float b0 = bias[col], b1 = bias[col + 1];
                    v00 += b0; v01 += b1; v10 += b0; v11 += b1;
                }
                float2 o0 = {v00 + r0.x, v01 + r0.y};
                float2 o1 = {v10 + r1.x, v11 + r1.y};
                *(float2*)(C + (size_t)row * ldc + col) = o0;
                *(float2*)(C + (size_t)(row + 8) * ldc + col) = o1;
            }
        }
    }
}

// ===== scores: P = bf16(exp2(Q'·K^T)), column partial sums per q-block ===========
#define SC_SMEM_BYTES (36864 + 1024)

__global__ void __launch_bounds__(256, 2) scores_bf() {
    extern __shared__ uint32_t smem[];
    const int tid = threadIdx.x;
    const int wid = tid >> 5, lane = tid & 31;
    const int wm = wid >> 2, wn = wid & 3;
    const int grp = lane >> 2, kq = lane & 3;
    const int bh = blockIdx.z, b = bh >> 4, h = bh & 15;
    const int q0 = blockIdx.y * 128, s0 = blockIdx.x * 128;

    const __nv_bfloat16* Ab = g_QKVh + (size_t)(b * TT + q0) * QKVN + h * DKK;
    const __nv_bfloat16* Bb = g_QKVh + (size_t)(b * TT + s0) * QKVN + 1024 + h * DKK;
    const uint32_t sbase = smem_to_u32(smem);
    const uint32_t sB0 = sbase + 18432u;

#pragma unroll
    for (int j = 0; j < 4; j++) {
        int idx = tid + j * 256;
        int rr = idx >> 3, seg = idx & 7;
        cpasync16(sbase + rr * 144u + seg * 16u, Ab + (size_t)rr * QKVN + seg * 8);
        cpasync16(sB0 + rr * 144u + seg * 16u, Bb + (size_t)rr * QKVN + seg * 8);
    }
    CP_COMMIT(); CP_WAIT(0);
    __syncthreads();

    float acc[4][4][4] = {};
    const uint32_t* As = smem;
    const uint32_t* Bs = smem + 4608;
#pragma unroll
    for (int ks = 0; ks < 4; ks++) {
        const int k0 = ks * 8;
        uint32_t bf[4][2];
#pragma unroll
        for (int ni = 0; ni < 4; ni++) {
            int nrow = wn * 32 + ni * 8 + grp;
            bf[ni][0] = Bs[nrow * 36 + k0 + kq];
            bf[ni][1] = Bs[nrow * 36 + k0 + kq + 4];
        }
#pragma unroll
        for (int mi = 0; mi < 4; mi++) {
            int mrow = wm * 64 + mi * 16 + grp;
            uint32_t a0 = As[mrow * 36 + k0 + kq];
            uint32_t a1 = As[(mrow + 8) * 36 + k0 + kq];
            uint32_t a2 = As[mrow * 36 + k0 + kq + 4];
            uint32_t a3 = As[(mrow + 8) * 36 + k0 + kq + 4];
#pragma unroll
            for (int ni = 0; ni < 4; ni++)
                mma_bf16(acc[mi][ni], a0, a1, a2, a3, bf[ni][0], bf[ni][1]);
        }
    }
    __syncthreads();

    float* zsm = (float*)(smem + 9216);   // [2][128]
    __nv_bfloat16* Sb = g_Sh + (size_t)bh * TT * TT;
    float cs0[4] = {}, cs1[4] = {};
#pragma unroll
    for (int mi = 0; mi < 4; mi++) {
        int row = q0 + wm * 64 + mi * 16 + grp;
#pragma unroll
        for (int ni = 0; ni < 4; ni++) {
            int col = s0 + wn * 32 + ni * 8 + kq * 2;
            float p00 = ex2f(acc[mi][ni][0]);
            float p01 = ex2f(acc[mi][ni][1]);
            float p10 = ex2f(acc[mi][ni][2]);
            float p11 = ex2f(acc[mi][ni][3]);
            cs0[ni] += p00 + p10;
            cs1[ni] += p01 + p11;
            *(uint32_t*)(Sb + (size_t)row * TT + col) = pack_bf162(p00, p01);
            *(uint32_t*)(Sb + (size_t)(row + 8) * TT + col) = pack_bf162(p10, p11);
        }
    }
#pragma unroll
    for (int ni = 0; ni < 4; ni++) {
#pragma unroll
        for (int o = 16; o >= 4; o >>= 1) {
            cs0[ni] += __shfl_down_sync(0xffffffffu, cs0[ni], o);
            cs1[ni] += __shfl_down_sync(0xffffffffu, cs1[ni], o);
        }
        if (grp == 0) {
            int c = wn * 32 + ni * 8 + kq * 2;
            zsm[wm * 128 + c] = cs0[ni];
            zsm[wm * 128 + c + 1] = cs1[ni];
        }
    }
    __syncthreads();
    if (tid < 128)
        g_zpart[(bh * 8 + blockIdx.y) * TT + s0 + tid] = zsm[tid] + zsm[128 + tid];
}

// ===== zinv reduce ================================================================
__global__ void __launch_bounds__(256) zinv_kernel() {
    int bh = blockIdx.x;
#pragma unroll
    for (int j = 0; j < 4; j++) {
        int s = threadIdx.x + j * 256;
        float z = 0.f;
#pragma unroll
        for (int q = 0; q < 8; q++) z += g_zpart[(bh * 8 + q) * TT + s];
        g_zinv[bh * TT + s] = 1.f / z;
    }
}

// ===== V' transpose: g_Vth[bh][v][s] = bf16(V[b,s,h,v]*zinv[bh,s]) ===============
__global__ void __launch_bounds__(256) vz_kernel() {
    __shared__ float sm[64][132];
    int bh = blockIdx.y, b = bh >> 4, h = bh & 15;
    int s0 = blockIdx.x * 128;
    const __nv_bfloat16* Vb = g_QKVh + (size_t)(b * TT + s0) * QKVN + 2048 + h * DKK;
    const float* zb = g_zinv + bh * TT + s0;
    int tid = threadIdx.x;
#pragma unroll
    for (int t = 0; t < 16; t++) {
        int idx = tid + t * 256;
        int r = idx >> 5, c2 = (idx & 31) * 2;
        __nv_bfloat162 v2 = *(const __nv_bfloat162*)(Vb + (size_t)r * QKVN + c2);
        float2 vf = __bfloat1622float2(v2);
        float zi = zb[r];
        sm[c2 + 0][r] = vf.x * zi;
        sm[c2 + 1][r] = vf.y * zi;
    }
    __syncthreads();
    __nv_bfloat16* Vt = g_Vth + (size_t)bh * DKK * TT + s0;
#pragma unroll
    for (int t = 0; t < 16; t++) {
        int idx = tid + t * 256;
        int v = idx >> 6, s2 = (idx & 63) * 2;
        *(uint32_t*)(Vt + (size_t)v * TT + s2) = pack_bf162(sm[v][s2], sm[v][s2 + 1]);
    }
}

// ===== AV GEMM (bf16): part[q][h*64+v] = sum_s P[q,s] * V'[v,s] ==================
#define AV_SMEM_BYTES 55296

__global__ void __launch_bounds__(256, 2) av_bf() {
    extern __shared__ uint32_t smem[];
    const int tid = threadIdx.x;
    const int wid = tid >> 5, lane = tid & 31;
    const int wm = wid >> 1, wn = wid & 1;
    const int grp = lane >> 2, kq = lane & 3;
    const int bh = blockIdx.y, b = bh >> 4, h = bh & 15;
    const int m0 = blockIdx.x * 128;

    const __nv_bfloat16* Ab = g_Sh + (size_t)bh * TT * TT + (size_t)m0 * TT;
    const __nv_bfloat16* Bb = g_Vth + (size_t)bh * DKK * TT;
    const uint32_t sbase = smem_to_u32(smem);

    float acc[2][4][4] = {};
    const int lr = tid >> 3, lseg = tid & 7;

    auto issue = [&](int c, int buf) {
        const int k0 = c * 64;
        const uint32_t sA = sbase + buf * 27648u;
        const uint32_t sB = sA + 18432u;
#pragma unroll
        for (int j = 0; j < 4; j++) {
            int rr = lr + j * 32;
            cpasync16(sA + rr * 144u + lseg * 16u, Ab + (size_t)rr * TT + k0 + lseg * 8);
        }
#pragma unroll
        for (int j = 0; j < 2; j++) {
            int rr = lr + j * 32;
            cpasync16(sB + rr * 144u + lseg * 16u, Bb + (size_t)rr * TT + k0 + lseg * 8);
        }
    };

    issue(0, 0);
    CP_COMMIT();

    for (int c = 0; c < 16; c++) {
        const int buf = c & 1;
        if (c + 1 < 16) { issue(c + 1, buf ^ 1); CP_COMMIT(); CP_WAIT(1); }
        else            { CP_WAIT(0); }
        __syncthreads();
        const uint32_t* As = smem + buf * 6912;
        const uint32_t* Bs = As + 4608;
#pragma unroll
        for (int ks = 0; ks < 4; ks++) {
            const int k0 = ks * 8;
            uint32_t bf[4][2];
#pragma unroll
            for (int ni = 0; ni < 4; ni++) {
                int nrow = wn * 32 + ni * 8 + grp;
                bf[ni][0] = Bs[nrow * 36 + k0 + kq];
                bf[ni][1] = Bs[nrow * 36 + k0 + kq + 4];
            }
#pragma unroll
            for (int mi = 0; mi < 2; mi++) {
                int mrow = wm * 32 + mi * 16 + grp;
                uint32_t a0 = As[mrow * 36 + k0 + kq];
                uint32_t a1 = As[(mrow + 8) * 36 + k0 + kq];
                uint32_t a2 = As[mrow * 36 + k0 + kq + 4];
                uint32_t a3 = As[(mrow + 8) * 36 + k0 + kq + 4];
#pragma unroll
                for (int ni = 0; ni < 4; ni++)
                    mma_bf16(acc[mi][ni], a0, a1, a2, a3, bf[ni][0], bf[ni][1]);
            }
        }
        __syncthreads();
    }

#pragma unroll
    for (int mi = 0; mi < 2; mi++) {
        int row = b * TT + m0 + wm * 32 + mi * 16 + grp;
#pragma unroll
        for (int ni = 0; ni < 4; ni++) {
            int col = h * DKK + wn * 32 + ni * 8 + kq * 2;
            *(uint32_t*)(g_parth + (size_t)row * DM + col)
                = pack_bf162(acc[mi][ni][0], acc[mi][ni][1]);
            *(uint32_t*)(g_parth + (size_t)(row + 8) * DM + col)
                = pack_bf162(acc[mi][ni][2], acc[mi][ni][3]);
        }
    }
}

// ---------------- producers / repacks --------------------------------------------
__global__ void __launch_bounds__(256) round_xh(const float* __restrict__ x) {
    int i = blockIdx.x * 256 + threadIdx.x;
    g_xh[i] = __float2bfloat16(x[i]);
}
__global__ void __launch_bounds__(256) repack_qkv3h(const float* __restrict__ Wq,
                                                    const float* __restrict__ Wk,
                                                    const float* __restrict__ Wv) {
    const float QSCALE = 0.125f * 1.4426950408889634f;   // (1/8)*log2(e)
    int i = blockIdx.x * 256 + threadIdx.x;
    int n = i >> 10, d = i & 1023;
    int hh = (n & 1023) >> 6, kk = n & 63;
    int src = (hh * DM + d) * DKK + kk;
    float v;
    if (n < 1024)      v = Wq[src] * QSCALE;
    else if (n < 2048) v = Wk[src];
    else               v = Wv[src];
    g_Wqkvh[i] = __float2bfloat16(v);
}
__global__ void __launch_bounds__(256) repack_woh(const float* __restrict__ Wo) {
    int i = blockIdx.x * 256 + threadIdx.x;
    int n = i >> 10, k = i & 1023;
    g_Worh[i] = __float2bfloat16(Wo[k * DM + n]);
}
__global__ void __launch_bounds__(256) repack_w12h(const float* __restrict__ W1,
                                                   const float* __restrict__ W2) {
    int i = blockIdx.x * 256 + threadIdx.x;
    g_W1h[i] = __float2half(W1[i]);
    g_W2h[i] = __float2half(W2[i]);
}

// ---------------- pseudo-norm ----------------------------------------------------
// MODE 0: fp32 out only.  MODE 1: fp32 out + fp16 out (for FF GEMM A).
template <int MODE>
__global__ void __launch_bounds__(256) pnorm_kernel(const float* __restrict__ in,
                                                    float* __restrict__ out,
                                                    __half* __restrict__ outh) {
    int row = blockIdx.x;
    const float* p = in + (size_t)row * DM;
    float s = 0.f, s2 = 0.f;
    for (int i = threadIdx.x; i < DM; i += 256) {
        float v = p[i];
        s += v;
        s2 = fmaf(v, v, s2);
    }
    __shared__ float sh[2][8];
#pragma unroll
    for (int o = 16; o > 0; o >>= 1) {
        s  += __shfl_down_sync(0xffffffffu, s, o);
        s2 += __shfl_down_sync(0xffffffffu, s2, o);
    }
    int wid = threadIdx.x >> 5, lane = threadIdx.x & 31;
    if (lane == 0) { sh[0][wid] = s; sh[1][wid] = s2; }
    __syncthreads();
    __shared__ float bsub;
    if (threadIdx.x == 0) {
        float ts = 0.f, ts2 = 0.f;
#pragma unroll
        for (int i = 0; i < 8; i++) { ts += sh[0][i]; ts2 += sh[1][i]; }
        float mean = ts * (1.f / 1024.f);
        float var = (ts2 - 1024.f * mean * mean) * (1.f / 1023.f);
        bsub = mean + sqrtf(fmaxf(var, 0.f));
    }
    __syncthreads();
    float sub = bsub;
    for (int i = threadIdx.x; i < DM; i += 256) {
        float v = p[i] - sub;
        out[(size_t)row * DM + i] = v;
        if (MODE == 1) outh[(size_t)row * DM + i] = __float2half(v);
    }
}

// ---------------- launch ----------------------------------------------------------
extern "C" void kernel_launch(void* const* d_in, const int* in_sizes, int n_in,
                              void* d_out, int out_size) {
    const float* x  = (const float*)d_in[0];
    const float* Wq = (const float*)d_in[1];
    const float* Wk = (const float*)d_in[2];
    const float* Wv = (const float*)d_in[3];
    const float* Wo = (const float*)d_in[4];
    const float* W1 = (const float*)d_in[5];
    const float* b1 = (const float*)d_in[6];
    const float* W2 = (const float*)d_in[7];
    const float* b2 = (const float*)d_in[8];
    float* out = (float*)d_out;

    __nv_bfloat16 *pXh, *pWqkvh, *pWorh, *pQKVh, *pParth;
    __half *pW1h, *pW2h, *pOut1h, *pFfhh;
    float *pOut1, *pOut2;
    cudaGetSymbolAddress((void**)&pXh,    g_xh);
    cudaGetSymbolAddress((void**)&pWqkvh, g_Wqkvh);
    cudaGetSymbolAddress((void**)&pWorh,  g_Worh);
    cudaGetSymbolAddress((void**)&pQKVh,  g_QKVh);
    cudaGetSymbolAddress((void**)&pParth, g_parth);
    cudaGetSymbolAddress((void**)&pW1h,   g_W1h);
    cudaGetSymbolAddress((void**)&pW2h,   g_W2h);
    cudaGetSymbolAddress((void**)&pOut1h, g_out1h);
    cudaGetSymbolAddress((void**)&pFfhh,  g_ffhh);
    cudaGetSymbolAddress((void**)&pOut1,  g_out1);
    cudaGetSymbolAddress((void**)&pOut2,  g_out2);

    cudaFuncSetAttribute((const void*)gemm_h<4,0>, cudaFuncAttributeMaxDynamicSharedMemorySize, GM_SMEM_BYTES);
    cudaFuncSetAttribute((const void*)gemm_h<1,0>, cudaFuncAttributeMaxDynamicSharedMemorySize, GM_SMEM_BYTES);
    cudaFuncSetAttribute((const void*)gemm_h<2,1>, cudaFuncAttributeMaxDynamicSharedMemorySize, GM_SMEM_BYTES);
    cudaFuncSetAttribute((const void*)gemm_h<3,1>, cudaFuncAttributeMaxDynamicSharedMemorySize, GM_SMEM_BYTES);
    cudaFuncSetAttribute(scores_bf, cudaFuncAttributeMaxDynamicSharedMemorySize, SC_SMEM_BYTES);
    cudaFuncSetAttribute(av_bf,     cudaFuncAttributeMaxDynamicSharedMemorySize, AV_SMEM_BYTES);

    // producers
    round_xh<<<BT * DM / 256, 256>>>(x);
    repack_qkv3h<<<QKVN * DM / 256, 256>>>(Wq, Wk, Wv);
    repack_woh<<<DM * DM / 256, 256>>>(Wo);
    repack_w12h<<<FFI * DM / 256, 256>>>(W1, W2);

    // fused QKV projection (bf16)
    gemm_h<4,0><<<dim3(QKVN / 128, BT / 128), 256, GM_SMEM_BYTES>>>(
        pXh, DM, pWqkvh, DM, pQKVh, QKVN, DM, nullptr, nullptr, 0);

    // attention (bf16)
    scores_bf<<<dim3(8, 8, BHN), 256, SC_SMEM_BYTES>>>();
    zinv_kernel<<<BHN, 256>>>();
    vz_kernel<<<dim3(8, BHN), 256>>>();
    av_bf<<<dim3(8, BHN), 256, AV_SMEM_BYTES>>>();

    // Wo (bf16) + residual (fp32 x) -> out1 fp32; pnorm emits fp32 + fp16
    gemm_h<1,0><<<dim3(DM / 128, BT / 128), 256, GM_SMEM_BYTES>>>(
        pParth, DM, pWorh, DM, pOut1, DM, DM, nullptr, x, DM);
    pnorm_kernel<1><<<BT, 256>>>(pOut1, pOut1, pOut1h);

    // FF (fp16)
    gemm_h<2,1><<<dim3(FFI / 128, BT / 128), 256, GM_SMEM_BYTES>>>(
        pOut1h, DM, pW1h, DM, pFfhh, FFI, DM, b1, nullptr, 0);
    gemm_h<3,1><<<dim3(DM / 128, BT / 128), 256, GM_SMEM_BYTES>>>(
        pFfhh, FFI, pW2h, FFI, pOut2, DM, FFI, b2, pOut1, DM);

    // final pseudo-norm -> output
    pnorm_kernel<0><<<BT, 256>>>(pOut2, out, nullptr);
}